// round 1
// baseline (speedup 1.0000x reference)
#include <cuda_runtime.h>
#include <math.h>

// Problem constants (fixed by setup_inputs)
#define Nn   4096     // G*K nodes
#define Gg   256
#define Kk   16
#define Ll   3
#define Hh   3
#define Ff   64
#define EMBd 200
#define HIDd 256
#define Ee   61440    // G*K*(K-1)
#define DEG  15       // edges per node (contiguous block [n*15, n*15+15))

// Scratch (global device memory, no allocation at runtime)
__device__ float g_fea[Nn * Ff];            // node features, updated per layer
__device__ float g_gate[Hh * Ee];           // per-layer edge gate scalars
__device__ float g_msg[Hh * Ee * Ff];       // per-layer edge messages (~47MB)
__device__ float g_gate_c[Hh * Nn];         // cry-pool node gate
__device__ float g_msg_c[Hh * Nn * Ff];     // cry-pool node messages

__device__ __forceinline__ float selu_f(float x) {
    const float scale = 1.0507009873554805f;
    const float alpha = 1.6732632423543772f;
    return x > 0.f ? scale * x : scale * alpha * (expf(x) - 1.f);
}

// ---------------------------------------------------------------------------
// Kernel 1: initial embed  fea = [elem_fea_in @ W_init + b_init, w]
// grid = N blocks, 64 threads (thread = output feature)
// ---------------------------------------------------------------------------
__global__ void embed_kernel(const float* __restrict__ ew,
                             const float* __restrict__ efea,
                             const float* __restrict__ Wi,
                             const float* __restrict__ bi) {
    __shared__ float sx[EMBd];
    const int n = blockIdx.x;
    const int t = threadIdx.x;  // 64
    for (int i = t; i < EMBd; i += 64) sx[i] = efea[n * EMBd + i];
    __syncthreads();
    if (t < Ff - 1) {
        float acc = bi[t];
        #pragma unroll 4
        for (int k = 0; k < EMBd; k++) acc = fmaf(sx[k], Wi[k * (Ff - 1) + t], acc);
        g_fea[n * Ff + t] = acc;
    } else {
        g_fea[n * Ff + t] = ew[n];  // t == 63: fractional weight channel
    }
}

// ---------------------------------------------------------------------------
// Kernel 2: fused edge MLPs for one layer, all heads (blockIdx.y = head).
// 64-edge tile per block, 256 threads. Thread t = hidden unit for the two
// 128->256 SELU layers; then re-mapped (f, edge-group) for the 256->64 GEMM.
// Produces g_gate[h,e] and g_msg[h,e,f]; no HBM intermediate for hidden.
// Dynamic smem: pair 32KB + hid 64KB + sg 256B.
// ---------------------------------------------------------------------------
__global__ void __launch_bounds__(256, 2)
edge_kernel(const float* __restrict__ gW1, const float* __restrict__ gb1,
            const float* __restrict__ gW2, const float* __restrict__ gb2,
            const float* __restrict__ mW1, const float* __restrict__ mb1,
            const float* __restrict__ mW2, const float* __restrict__ mb2,
            const int* __restrict__ self_idx, const int* __restrict__ nbr_idx,
            int layer) {
    extern __shared__ float smem[];
    float* spair = smem;                 // [64][128]
    float* shid  = smem + 64 * 128;      // [64][256]
    float* sg    = shid + 64 * HIDd;     // [64]

    const int h  = blockIdx.y;
    const int e0 = blockIdx.x * 64;
    const int t  = threadIdx.x;
    const int lh = layer * Hh + h;

    // gather pair = [fea[self], fea[nbr]]
    for (int idx = t; idx < 64 * 128; idx += 256) {
        const int e = idx >> 7, c = idx & 127;
        const int ge  = e0 + e;
        const int row = (c < Ff) ? self_idx[ge] : nbr_idx[ge];
        spair[idx] = g_fea[row * Ff + (c & (Ff - 1))];
    }
    if (t < 64) sg[t] = 0.f;
    __syncthreads();

    // ---- gate net: hidden = selu(pair @ gW1 + gb1); gate = hidden @ gW2 ----
    {
        const float* W1 = gW1 + lh * (2 * Ff * HIDd);
        float acc[64];
        const float b = gb1[lh * HIDd + t];
        #pragma unroll
        for (int e = 0; e < 64; e++) acc[e] = b;
        #pragma unroll 1
        for (int k = 0; k < 2 * Ff; k += 4) {
            const float w0 = W1[(k + 0) * HIDd + t];
            const float w1 = W1[(k + 1) * HIDd + t];
            const float w2 = W1[(k + 2) * HIDd + t];
            const float w3 = W1[(k + 3) * HIDd + t];
            #pragma unroll
            for (int e = 0; e < 64; e++) {
                const float4 p = *reinterpret_cast<const float4*>(&spair[e * 128 + k]);
                acc[e] = fmaf(p.x, w0, acc[e]);
                acc[e] = fmaf(p.y, w1, acc[e]);
                acc[e] = fmaf(p.z, w2, acc[e]);
                acc[e] = fmaf(p.w, w3, acc[e]);
            }
        }
        const float w2v = gW2[lh * HIDd + t];
        #pragma unroll
        for (int e = 0; e < 64; e++) {
            float v = selu_f(acc[e]) * w2v;
            #pragma unroll
            for (int o = 16; o; o >>= 1) v += __shfl_xor_sync(0xffffffffu, v, o);
            if ((t & 31) == 0) atomicAdd(&sg[e], v);
        }
    }

    // ---- msg net hidden: shid = selu(pair @ mW1 + mb1) ----
    {
        const float* W1 = mW1 + lh * (2 * Ff * HIDd);
        float acc[64];
        const float b = mb1[lh * HIDd + t];
        #pragma unroll
        for (int e = 0; e < 64; e++) acc[e] = b;
        #pragma unroll 1
        for (int k = 0; k < 2 * Ff; k += 4) {
            const float w0 = W1[(k + 0) * HIDd + t];
            const float w1 = W1[(k + 1) * HIDd + t];
            const float w2 = W1[(k + 2) * HIDd + t];
            const float w3 = W1[(k + 3) * HIDd + t];
            #pragma unroll
            for (int e = 0; e < 64; e++) {
                const float4 p = *reinterpret_cast<const float4*>(&spair[e * 128 + k]);
                acc[e] = fmaf(p.x, w0, acc[e]);
                acc[e] = fmaf(p.y, w1, acc[e]);
                acc[e] = fmaf(p.z, w2, acc[e]);
                acc[e] = fmaf(p.w, w3, acc[e]);
            }
        }
        #pragma unroll
        for (int e = 0; e < 64; e++) shid[e * HIDd + t] = selu_f(acc[e]);
    }
    __syncthreads();

    // gate writeout (+ gb2 scalar bias)
    if (t < 64) g_gate[h * Ee + e0 + t] = sg[t] + gb2[lh];

    // ---- msg out: MSG[e][f] = shid[e][:] . mW2[:,f] + mb2[f] ----
    {
        const float* W2 = mW2 + lh * (HIDd * Ff);
        const int f   = t & 63;
        const int grp = t >> 6;  // 4 groups of 16 edges
        float macc[16];
        const float b = mb2[lh * Ff + f];
        #pragma unroll
        for (int e = 0; e < 16; e++) macc[e] = b;
        #pragma unroll 2
        for (int k = 0; k < HIDd; k += 4) {
            const float w0 = W2[(k + 0) * Ff + f];
            const float w1 = W2[(k + 1) * Ff + f];
            const float w2 = W2[(k + 2) * Ff + f];
            const float w3 = W2[(k + 3) * Ff + f];
            #pragma unroll
            for (int e = 0; e < 16; e++) {
                const float4 hv =
                    *reinterpret_cast<const float4*>(&shid[(grp * 16 + e) * HIDd + k]);
                macc[e] = fmaf(hv.x, w0, macc[e]);
                macc[e] = fmaf(hv.y, w1, macc[e]);
                macc[e] = fmaf(hv.z, w2, macc[e]);
                macc[e] = fmaf(hv.w, w3, macc[e]);
            }
        }
        #pragma unroll
        for (int e = 0; e < 16; e++) {
            const int ge = e0 + grp * 16 + e;
            g_msg[(h * Ee + ge) * Ff + f] = macc[e];
        }
    }
}

// ---------------------------------------------------------------------------
// Kernel 3: per-node segment softmax (weighted by wn^pow) + weighted msg sum,
// mean over heads, residual add into fea. Edges for node n are contiguous.
// grid = N blocks, 64 threads (thread = feature).
// ---------------------------------------------------------------------------
__global__ void node_agg_kernel(const float* __restrict__ ew,
                                const int* __restrict__ nbr_idx,
                                const float* __restrict__ m_pow, int layer) {
    __shared__ float sattn[Hh][DEG];
    const int n = blockIdx.x, t = threadIdx.x;
    if (t < Hh) {
        const int h = t;
        const float pw = m_pow[layer * Hh + h];
        float gv[DEG];
        float gmax = -1e30f;
        #pragma unroll
        for (int j = 0; j < DEG; j++) {
            gv[j] = g_gate[h * Ee + n * DEG + j];
            gmax = fmaxf(gmax, gv[j]);
        }
        float den = 1e-10f;
        #pragma unroll
        for (int j = 0; j < DEG; j++) {
            const float wn = ew[nbr_idx[n * DEG + j]];
            const float a = powf(wn, pw) * expf(gv[j] - gmax);
            sattn[h][j] = a;
            den += a;
        }
        const float inv = 1.f / den;
        #pragma unroll
        for (int j = 0; j < DEG; j++) sattn[h][j] *= inv;
    }
    __syncthreads();
    float out = 0.f;
    #pragma unroll
    for (int h = 0; h < Hh; h++) {
        const float* mp = &g_msg[(h * Ee + n * DEG) * Ff + t];
        #pragma unroll
        for (int j = 0; j < DEG; j++) out = fmaf(sattn[h][j], mp[j * Ff], out);
    }
    g_fea[n * Ff + t] += out * (1.f / Hh);
}

// ---------------------------------------------------------------------------
// Kernel 4: cry-pool node MLPs (input dim 64). Same structure as edge_kernel.
// 64-node tile, 256 threads, blockIdx.y = head.
// ---------------------------------------------------------------------------
__global__ void __launch_bounds__(256, 2)
cry_node_kernel(const float* __restrict__ cgW1, const float* __restrict__ cgb1,
                const float* __restrict__ cgW2, const float* __restrict__ cgb2,
                const float* __restrict__ cmW1, const float* __restrict__ cmb1,
                const float* __restrict__ cmW2, const float* __restrict__ cmb2) {
    extern __shared__ float smem[];
    float* sx   = smem;                 // [64][64]
    float* shid = smem + 64 * 64;       // [64][256]
    float* sg   = shid + 64 * HIDd;     // [64]

    const int h  = blockIdx.y;
    const int n0 = blockIdx.x * 64;
    const int t  = threadIdx.x;

    for (int idx = t; idx < 64 * 64; idx += 256) sx[idx] = g_fea[n0 * Ff + idx];
    if (t < 64) sg[t] = 0.f;
    __syncthreads();

    // gate net
    {
        const float* W1 = cgW1 + h * (Ff * HIDd);
        float acc[64];
        const float b = cgb1[h * HIDd + t];
        #pragma unroll
        for (int e = 0; e < 64; e++) acc[e] = b;
        #pragma unroll 1
        for (int k = 0; k < Ff; k += 4) {
            const float w0 = W1[(k + 0) * HIDd + t];
            const float w1 = W1[(k + 1) * HIDd + t];
            const float w2 = W1[(k + 2) * HIDd + t];
            const float w3 = W1[(k + 3) * HIDd + t];
            #pragma unroll
            for (int e = 0; e < 64; e++) {
                const float4 p = *reinterpret_cast<const float4*>(&sx[e * Ff + k]);
                acc[e] = fmaf(p.x, w0, acc[e]);
                acc[e] = fmaf(p.y, w1, acc[e]);
                acc[e] = fmaf(p.z, w2, acc[e]);
                acc[e] = fmaf(p.w, w3, acc[e]);
            }
        }
        const float w2v = cgW2[h * HIDd + t];
        #pragma unroll
        for (int e = 0; e < 64; e++) {
            float v = selu_f(acc[e]) * w2v;
            #pragma unroll
            for (int o = 16; o; o >>= 1) v += __shfl_xor_sync(0xffffffffu, v, o);
            if ((t & 31) == 0) atomicAdd(&sg[e], v);
        }
    }
    // msg hidden
    {
        const float* W1 = cmW1 + h * (Ff * HIDd);
        float acc[64];
        const float b = cmb1[h * HIDd + t];
        #pragma unroll
        for (int e = 0; e < 64; e++) acc[e] = b;
        #pragma unroll 1
        for (int k = 0; k < Ff; k += 4) {
            const float w0 = W1[(k + 0) * HIDd + t];
            const float w1 = W1[(k + 1) * HIDd + t];
            const float w2 = W1[(k + 2) * HIDd + t];
            const float w3 = W1[(k + 3) * HIDd + t];
            #pragma unroll
            for (int e = 0; e < 64; e++) {
                const float4 p = *reinterpret_cast<const float4*>(&sx[e * Ff + k]);
                acc[e] = fmaf(p.x, w0, acc[e]);
                acc[e] = fmaf(p.y, w1, acc[e]);
                acc[e] = fmaf(p.z, w2, acc[e]);
                acc[e] = fmaf(p.w, w3, acc[e]);
            }
        }
        #pragma unroll
        for (int e = 0; e < 64; e++) shid[e * HIDd + t] = selu_f(acc[e]);
    }
    __syncthreads();

    if (t < 64) g_gate_c[h * Nn + n0 + t] = sg[t] + cgb2[h];

    // msg out
    {
        const float* W2 = cmW2 + h * (HIDd * Ff);
        const int f   = t & 63;
        const int grp = t >> 6;
        float macc[16];
        const float b = cmb2[h * Ff + f];
        #pragma unroll
        for (int e = 0; e < 16; e++) macc[e] = b;
        #pragma unroll 2
        for (int k = 0; k < HIDd; k += 4) {
            const float w0 = W2[(k + 0) * Ff + f];
            const float w1 = W2[(k + 1) * Ff + f];
            const float w2 = W2[(k + 2) * Ff + f];
            const float w3 = W2[(k + 3) * Ff + f];
            #pragma unroll
            for (int e = 0; e < 16; e++) {
                const float4 hv =
                    *reinterpret_cast<const float4*>(&shid[(grp * 16 + e) * HIDd + k]);
                macc[e] = fmaf(hv.x, w0, macc[e]);
                macc[e] = fmaf(hv.y, w1, macc[e]);
                macc[e] = fmaf(hv.z, w2, macc[e]);
                macc[e] = fmaf(hv.w, w3, macc[e]);
            }
        }
        #pragma unroll
        for (int e = 0; e < 16; e++) {
            const int n = n0 + grp * 16 + e;
            g_msg_c[(h * Nn + n) * Ff + f] = macc[e];
        }
    }
}

// ---------------------------------------------------------------------------
// Kernel 5: per-graph pooling (16 contiguous nodes), mean over heads -> out.
// grid = G blocks, 64 threads (thread = feature).
// ---------------------------------------------------------------------------
__global__ void cry_agg_kernel(const float* __restrict__ ew,
                               const float* __restrict__ c_pow,
                               float* __restrict__ out) {
    __shared__ float sattn[Hh][Kk];
    const int g = blockIdx.x, t = threadIdx.x;
    if (t < Hh) {
        const int h = t;
        const float pw = c_pow[h];
        float gv[Kk];
        float gmax = -1e30f;
        #pragma unroll
        for (int j = 0; j < Kk; j++) {
            gv[j] = g_gate_c[h * Nn + g * Kk + j];
            gmax = fmaxf(gmax, gv[j]);
        }
        float den = 1e-10f;
        #pragma unroll
        for (int j = 0; j < Kk; j++) {
            const float a = powf(ew[g * Kk + j], pw) * expf(gv[j] - gmax);
            sattn[h][j] = a;
            den += a;
        }
        const float inv = 1.f / den;
        #pragma unroll
        for (int j = 0; j < Kk; j++) sattn[h][j] *= inv;
    }
    __syncthreads();
    float o = 0.f;
    #pragma unroll
    for (int h = 0; h < Hh; h++) {
        const float* mp = &g_msg_c[(h * Nn + g * Kk) * Ff + t];
        #pragma unroll
        for (int j = 0; j < Kk; j++) o = fmaf(sattn[h][j], mp[j * Ff], o);
    }
    out[g * Ff + t] = o * (1.f / Hh);
}

// ---------------------------------------------------------------------------

extern "C" void kernel_launch(void* const* d_in, const int* in_sizes, int n_in,
                              void* d_out, int out_size) {
    const float* elem_weights = (const float*)d_in[0];
    const float* elem_fea_in  = (const float*)d_in[1];
    const float* W_init = (const float*)d_in[2];
    const float* b_init = (const float*)d_in[3];
    const float* mg_W1  = (const float*)d_in[4];
    const float* mg_b1  = (const float*)d_in[5];
    const float* mg_W2  = (const float*)d_in[6];
    const float* mg_b2  = (const float*)d_in[7];
    const float* mm_W1  = (const float*)d_in[8];
    const float* mm_b1  = (const float*)d_in[9];
    const float* mm_W2  = (const float*)d_in[10];
    const float* mm_b2  = (const float*)d_in[11];
    const float* m_pow  = (const float*)d_in[12];
    const float* cg_W1  = (const float*)d_in[13];
    const float* cg_b1  = (const float*)d_in[14];
    const float* cg_W2  = (const float*)d_in[15];
    const float* cg_b2  = (const float*)d_in[16];
    const float* cm_W1  = (const float*)d_in[17];
    const float* cm_b1  = (const float*)d_in[18];
    const float* cm_W2  = (const float*)d_in[19];
    const float* cm_b2  = (const float*)d_in[20];
    const float* c_pow  = (const float*)d_in[21];
    // d_in[22] = batch (implicit: n/16), unused
    const int* self_idx = (const int*)d_in[23];
    const int* nbr_idx  = (const int*)d_in[24];
    float* out = (float*)d_out;

    const int EDGE_SMEM = (64 * 128 + 64 * HIDd + 64) * (int)sizeof(float);  // 98560
    const int CRY_SMEM  = (64 * Ff + 64 * HIDd + 64) * (int)sizeof(float);   // 82176
    cudaFuncSetAttribute((const void*)edge_kernel,
                         cudaFuncAttributeMaxDynamicSharedMemorySize, EDGE_SMEM);
    cudaFuncSetAttribute((const void*)cry_node_kernel,
                         cudaFuncAttributeMaxDynamicSharedMemorySize, CRY_SMEM);

    embed_kernel<<<Nn, 64>>>(elem_weights, elem_fea_in, W_init, b_init);

    for (int l = 0; l < Ll; l++) {
        edge_kernel<<<dim3(Ee / 64, Hh), 256, EDGE_SMEM>>>(
            mg_W1, mg_b1, mg_W2, mg_b2, mm_W1, mm_b1, mm_W2, mm_b2,
            self_idx, nbr_idx, l);
        node_agg_kernel<<<Nn, 64>>>(elem_weights, nbr_idx, m_pow, l);
    }

    cry_node_kernel<<<dim3(Nn / 64, Hh), 256, CRY_SMEM>>>(
        cg_W1, cg_b1, cg_W2, cg_b2, cm_W1, cm_b1, cm_W2, cm_b2);
    cry_agg_kernel<<<Gg, 64>>>(elem_weights, c_pow, out);
}

// round 2
// speedup vs baseline: 1.1100x; 1.1100x over previous
#include <cuda_runtime.h>
#include <math.h>

// Problem constants (fixed by setup_inputs)
#define Nn   4096     // G*K nodes
#define Gg   256
#define Kk   16
#define Ll   3
#define Hh   3
#define Ff   64
#define EMBd 200
#define HIDd 256
#define Ee   61440    // G*K*(K-1)
#define DEG  15       // edges per node (contiguous block [n*15, n*15+15))
#define SP   72       // padded smem row stride (floats); 72*4B is 16B-aligned

// Scratch (global device memory, no allocation at runtime)
__device__ float g_fea[Nn * Ff];            // node features, updated per layer
__device__ float g_gate[Hh * Ee];           // per-layer edge gate scalars
__device__ float g_msg[Hh * Ee * Ff];       // per-layer edge messages
__device__ float g_gate_c[Hh * Nn];         // cry-pool node gate
__device__ float g_msg_c[Hh * Nn * Ff];     // cry-pool node messages

typedef unsigned long long u64;

__device__ __forceinline__ float selu_f(float x) {
    const float scale = 1.0507009873554805f;
    const float alpha = 1.6732632423543772f;
    return x > 0.f ? scale * x : scale * alpha * (expf(x) - 1.f);
}

__device__ __forceinline__ u64 pack2(float lo, float hi) {
    u64 r; asm("mov.b64 %0, {%1, %2};" : "=l"(r) : "f"(lo), "f"(hi)); return r;
}
__device__ __forceinline__ void unpack2(u64 v, float& a, float& b) {
    asm("mov.b64 {%0, %1}, %2;" : "=f"(a), "=f"(b) : "l"(v));
}
__device__ __forceinline__ u64 fma2(u64 a, u64 b, u64 c) {
    u64 d; asm("fma.rn.f32x2 %0, %1, %2, %3;" : "=l"(d) : "l"(a), "l"(b), "l"(c));
    return d;
}
__device__ __forceinline__ void lds128(u64& p01, u64& p23, unsigned addr) {
    asm volatile("ld.shared.v2.b64 {%0, %1}, [%2];"
                 : "=l"(p01), "=l"(p23) : "r"(addr));
}
__device__ __forceinline__ void sts128(unsigned addr, u64 p01, u64 p23) {
    asm volatile("st.shared.v2.b64 [%0], {%1, %2};"
                 :: "r"(addr), "l"(p01), "l"(p23));
}
__device__ __forceinline__ unsigned sm_u32(const void* p) {
    unsigned r;
    asm("{ .reg .u64 t; cvta.to.shared.u64 t, %1; cvt.u32.u64 %0, t; }"
        : "=r"(r) : "l"(p));
    return r;
}

// ---------------------------------------------------------------------------
// Kernel 1: initial embed  fea = [elem_fea_in @ W_init + b_init, w]
// ---------------------------------------------------------------------------
__global__ void embed_kernel(const float* __restrict__ ew,
                             const float* __restrict__ efea,
                             const float* __restrict__ Wi,
                             const float* __restrict__ bi) {
    __shared__ float sx[EMBd];
    const int n = blockIdx.x;
    const int t = threadIdx.x;  // 64
    for (int i = t; i < EMBd; i += 64) sx[i] = efea[n * EMBd + i];
    __syncthreads();
    if (t < Ff - 1) {
        float acc = bi[t];
        #pragma unroll 4
        for (int k = 0; k < EMBd; k++) acc = fmaf(sx[k], Wi[k * (Ff - 1) + t], acc);
        g_fea[n * Ff + t] = acc;
    } else {
        g_fea[n * Ff + t] = ew[n];  // t == 63: fractional weight channel
    }
}

// ---------------------------------------------------------------------------
// Kernel 2: fused edge MLPs for one layer, one head (blockIdx.y = head).
// 64-edge tile per block, 512 threads = 256 hidden units x 2 edge-halves.
// spair/shid stored k-major (transposed, stride SP) so a single LDS.128
// yields two f32x2 operands covering 4 edges at one k. Gate and msg W1
// passes fused to share every spair read. FFMA2 throughout.
// ---------------------------------------------------------------------------
__global__ void __launch_bounds__(512, 1)
edge_kernel(const float* __restrict__ gW1, const float* __restrict__ gb1,
            const float* __restrict__ gW2, const float* __restrict__ gb2,
            const float* __restrict__ mW1, const float* __restrict__ mb1,
            const float* __restrict__ mW2, const float* __restrict__ mb2,
            const int* __restrict__ self_idx, const int* __restrict__ nbr_idx,
            int layer) {
    extern __shared__ float smem[];
    float* spair = smem;                        // [128][SP]  (k-major)
    float* shid  = smem + 128 * SP;             // [256][SP]  (k-major)
    float* sg    = smem + 128 * SP + 256 * SP;  // [64]

    const int h  = blockIdx.y;
    const int e0 = blockIdx.x * 64;
    const int t  = threadIdx.x;
    const int th   = t & 255;   // hidden unit
    const int half = t >> 8;    // edge half (0/1)
    const int eb   = half * 32; // this thread's 32 edges start
    const int lh = layer * Hh + h;

    // gather pair = [fea[self], fea[nbr]] into transposed layout
    for (int idx = t; idx < 64 * 128; idx += 512) {
        const int e = idx >> 7, c = idx & 127;
        const int ge  = e0 + e;
        const int row = (c < Ff) ? self_idx[ge] : nbr_idx[ge];
        spair[c * SP + e] = g_fea[row * Ff + (c & (Ff - 1))];
    }
    if (t < 64) sg[t] = 0.f;
    __syncthreads();

    // ---- fused W1 passes: gate hidden + msg hidden share every LDS ----
    u64 ag[16], am[16];
    {
        const float bg = gb1[lh * HIDd + th];
        const float bm = mb1[lh * HIDd + th];
        const u64 bg2 = pack2(bg, bg), bm2 = pack2(bm, bm);
        #pragma unroll
        for (int i = 0; i < 16; i++) { ag[i] = bg2; am[i] = bm2; }
    }
    {
        const float* Wg = gW1 + lh * (2 * Ff * HIDd) + th;
        const float* Wm = mW1 + lh * (2 * Ff * HIDd) + th;
        const unsigned spair_a = sm_u32(spair) + eb * 4;
        #pragma unroll 2
        for (int k = 0; k < 2 * Ff; k++) {
            const float wg = Wg[k * HIDd];
            const float wm = Wm[k * HIDd];
            const u64 wg2 = pack2(wg, wg);
            const u64 wm2 = pack2(wm, wm);
            const unsigned a = spair_a + k * (SP * 4);
            #pragma unroll
            for (int j = 0; j < 8; j++) {
                u64 p01, p23;
                lds128(p01, p23, a + j * 16);
                ag[2 * j]     = fma2(p01, wg2, ag[2 * j]);
                ag[2 * j + 1] = fma2(p23, wg2, ag[2 * j + 1]);
                am[2 * j]     = fma2(p01, wm2, am[2 * j]);
                am[2 * j + 1] = fma2(p23, wm2, am[2 * j + 1]);
            }
        }
    }

    // ---- gate: selu, * gW2[th], reduce over 256 hidden units per edge ----
    {
        const float w2v = gW2[lh * HIDd + th];
        #pragma unroll
        for (int i = 0; i < 16; i++) {
            float a0, a1; unpack2(ag[i], a0, a1);
            float v0 = selu_f(a0) * w2v;
            float v1 = selu_f(a1) * w2v;
            #pragma unroll
            for (int o = 16; o; o >>= 1) {
                v0 += __shfl_xor_sync(0xffffffffu, v0, o);
                v1 += __shfl_xor_sync(0xffffffffu, v1, o);
            }
            if ((t & 31) == 0) {
                atomicAdd(&sg[eb + 2 * i],     v0);
                atomicAdd(&sg[eb + 2 * i + 1], v1);
            }
        }
    }

    // ---- msg hidden: selu + store transposed ----
    {
        #pragma unroll
        for (int i = 0; i < 16; i++) {
            float a0, a1; unpack2(am[i], a0, a1);
            am[i] = pack2(selu_f(a0), selu_f(a1));
        }
        const unsigned sa = sm_u32(shid) + (th * SP + eb) * 4;
        #pragma unroll
        for (int j = 0; j < 8; j++) sts128(sa + j * 16, am[2 * j], am[2 * j + 1]);
    }
    __syncthreads();

    if (t < 64) g_gate[h * Ee + e0 + t] = sg[t] + gb2[lh];

    // ---- msg out: MSG[e][f] = shid_T[:,e] . mW2[:,f] + mb2[f] ----
    {
        const float* W2 = mW2 + lh * (HIDd * Ff);
        const int f  = t & 63;
        const int g8 = t >> 6;   // 8 groups of 8 edges
        u64 acc[4];
        {
            const float b = mb2[lh * Ff + f];
            const u64 b2 = pack2(b, b);
            acc[0] = acc[1] = acc[2] = acc[3] = b2;
        }
        const unsigned sa = sm_u32(shid) + (g8 * 8) * 4;
        #pragma unroll 4
        for (int k = 0; k < HIDd; k++) {
            const float w = W2[k * Ff + f];
            const u64 w2 = pack2(w, w);
            u64 p01, p23, p45, p67;
            lds128(p01, p23, sa + k * (SP * 4));
            lds128(p45, p67, sa + k * (SP * 4) + 16);
            acc[0] = fma2(p01, w2, acc[0]);
            acc[1] = fma2(p23, w2, acc[1]);
            acc[2] = fma2(p45, w2, acc[2]);
            acc[3] = fma2(p67, w2, acc[3]);
        }
        #pragma unroll
        for (int i = 0; i < 4; i++) {
            float a0, a1; unpack2(acc[i], a0, a1);
            const int ge = e0 + g8 * 8 + 2 * i;
            g_msg[(h * Ee + ge) * Ff + f]     = a0;
            g_msg[(h * Ee + ge + 1) * Ff + f] = a1;
        }
    }
}

// ---------------------------------------------------------------------------
// Kernel 3: per-node segment softmax + weighted msg sum, mean over heads,
// residual add. Edges for node n are contiguous (DEG=15).
// ---------------------------------------------------------------------------
__global__ void node_agg_kernel(const float* __restrict__ ew,
                                const int* __restrict__ nbr_idx,
                                const float* __restrict__ m_pow, int layer) {
    __shared__ float sattn[Hh][DEG];
    const int n = blockIdx.x, t = threadIdx.x;
    if (t < Hh) {
        const int h = t;
        const float pw = m_pow[layer * Hh + h];
        float gv[DEG];
        float gmax = -1e30f;
        #pragma unroll
        for (int j = 0; j < DEG; j++) {
            gv[j] = g_gate[h * Ee + n * DEG + j];
            gmax = fmaxf(gmax, gv[j]);
        }
        float den = 1e-10f;
        #pragma unroll
        for (int j = 0; j < DEG; j++) {
            const float wn = ew[nbr_idx[n * DEG + j]];
            const float a = powf(wn, pw) * expf(gv[j] - gmax);
            sattn[h][j] = a;
            den += a;
        }
        const float inv = 1.f / den;
        #pragma unroll
        for (int j = 0; j < DEG; j++) sattn[h][j] *= inv;
    }
    __syncthreads();
    float out = 0.f;
    #pragma unroll
    for (int h = 0; h < Hh; h++) {
        const float* mp = &g_msg[(h * Ee + n * DEG) * Ff + t];
        #pragma unroll
        for (int j = 0; j < DEG; j++) out = fmaf(sattn[h][j], mp[j * Ff], out);
    }
    g_fea[n * Ff + t] += out * (1.f / Hh);
}

// ---------------------------------------------------------------------------
// Kernel 4: cry-pool node MLPs (input dim 64). 64-node tile, 256 threads.
// ---------------------------------------------------------------------------
__global__ void __launch_bounds__(256, 2)
cry_node_kernel(const float* __restrict__ cgW1, const float* __restrict__ cgb1,
                const float* __restrict__ cgW2, const float* __restrict__ cgb2,
                const float* __restrict__ cmW1, const float* __restrict__ cmb1,
                const float* __restrict__ cmW2, const float* __restrict__ cmb2) {
    extern __shared__ float smem[];
    float* sx   = smem;                 // [64][64]
    float* shid = smem + 64 * 64;       // [64][256]
    float* sg   = shid + 64 * HIDd;     // [64]

    const int h  = blockIdx.y;
    const int n0 = blockIdx.x * 64;
    const int t  = threadIdx.x;

    for (int idx = t; idx < 64 * 64; idx += 256) sx[idx] = g_fea[n0 * Ff + idx];
    if (t < 64) sg[t] = 0.f;
    __syncthreads();

    // gate net
    {
        const float* W1 = cgW1 + h * (Ff * HIDd);
        float acc[64];
        const float b = cgb1[h * HIDd + t];
        #pragma unroll
        for (int e = 0; e < 64; e++) acc[e] = b;
        #pragma unroll 1
        for (int k = 0; k < Ff; k += 4) {
            const float w0 = W1[(k + 0) * HIDd + t];
            const float w1 = W1[(k + 1) * HIDd + t];
            const float w2 = W1[(k + 2) * HIDd + t];
            const float w3 = W1[(k + 3) * HIDd + t];
            #pragma unroll
            for (int e = 0; e < 64; e++) {
                const float4 p = *reinterpret_cast<const float4*>(&sx[e * Ff + k]);
                acc[e] = fmaf(p.x, w0, acc[e]);
                acc[e] = fmaf(p.y, w1, acc[e]);
                acc[e] = fmaf(p.z, w2, acc[e]);
                acc[e] = fmaf(p.w, w3, acc[e]);
            }
        }
        const float w2v = cgW2[h * HIDd + t];
        #pragma unroll
        for (int e = 0; e < 64; e++) {
            float v = selu_f(acc[e]) * w2v;
            #pragma unroll
            for (int o = 16; o; o >>= 1) v += __shfl_xor_sync(0xffffffffu, v, o);
            if ((t & 31) == 0) atomicAdd(&sg[e], v);
        }
    }
    // msg hidden
    {
        const float* W1 = cmW1 + h * (Ff * HIDd);
        float acc[64];
        const float b = cmb1[h * HIDd + t];
        #pragma unroll
        for (int e = 0; e < 64; e++) acc[e] = b;
        #pragma unroll 1
        for (int k = 0; k < Ff; k += 4) {
            const float w0 = W1[(k + 0) * HIDd + t];
            const float w1 = W1[(k + 1) * HIDd + t];
            const float w2 = W1[(k + 2) * HIDd + t];
            const float w3 = W1[(k + 3) * HIDd + t];
            #pragma unroll
            for (int e = 0; e < 64; e++) {
                const float4 p = *reinterpret_cast<const float4*>(&sx[e * Ff + k]);
                acc[e] = fmaf(p.x, w0, acc[e]);
                acc[e] = fmaf(p.y, w1, acc[e]);
                acc[e] = fmaf(p.z, w2, acc[e]);
                acc[e] = fmaf(p.w, w3, acc[e]);
            }
        }
        #pragma unroll
        for (int e = 0; e < 64; e++) shid[e * HIDd + t] = selu_f(acc[e]);
    }
    __syncthreads();

    if (t < 64) g_gate_c[h * Nn + n0 + t] = sg[t] + cgb2[h];

    // msg out
    {
        const float* W2 = cmW2 + h * (HIDd * Ff);
        const int f   = t & 63;
        const int grp = t >> 6;
        float macc[16];
        const float b = cmb2[h * Ff + f];
        #pragma unroll
        for (int e = 0; e < 16; e++) macc[e] = b;
        #pragma unroll 2
        for (int k = 0; k < HIDd; k += 4) {
            const float w0 = W2[(k + 0) * Ff + f];
            const float w1 = W2[(k + 1) * Ff + f];
            const float w2 = W2[(k + 2) * Ff + f];
            const float w3 = W2[(k + 3) * Ff + f];
            #pragma unroll
            for (int e = 0; e < 16; e++) {
                const float4 hv =
                    *reinterpret_cast<const float4*>(&shid[(grp * 16 + e) * HIDd + k]);
                macc[e] = fmaf(hv.x, w0, macc[e]);
                macc[e] = fmaf(hv.y, w1, macc[e]);
                macc[e] = fmaf(hv.z, w2, macc[e]);
                macc[e] = fmaf(hv.w, w3, macc[e]);
            }
        }
        #pragma unroll
        for (int e = 0; e < 16; e++) {
            const int n = n0 + grp * 16 + e;
            g_msg_c[(h * Nn + n) * Ff + f] = macc[e];
        }
    }
}

// ---------------------------------------------------------------------------
// Kernel 5: per-graph pooling (16 contiguous nodes), mean over heads -> out.
// ---------------------------------------------------------------------------
__global__ void cry_agg_kernel(const float* __restrict__ ew,
                               const float* __restrict__ c_pow,
                               float* __restrict__ out) {
    __shared__ float sattn[Hh][Kk];
    const int g = blockIdx.x, t = threadIdx.x;
    if (t < Hh) {
        const int h = t;
        const float pw = c_pow[h];
        float gv[Kk];
        float gmax = -1e30f;
        #pragma unroll
        for (int j = 0; j < Kk; j++) {
            gv[j] = g_gate_c[h * Nn + g * Kk + j];
            gmax = fmaxf(gmax, gv[j]);
        }
        float den = 1e-10f;
        #pragma unroll
        for (int j = 0; j < Kk; j++) {
            const float a = powf(ew[g * Kk + j], pw) * expf(gv[j] - gmax);
            sattn[h][j] = a;
            den += a;
        }
        const float inv = 1.f / den;
        #pragma unroll
        for (int j = 0; j < Kk; j++) sattn[h][j] *= inv;
    }
    __syncthreads();
    float o = 0.f;
    #pragma unroll
    for (int h = 0; h < Hh; h++) {
        const float* mp = &g_msg_c[(h * Nn + g * Kk) * Ff + t];
        #pragma unroll
        for (int j = 0; j < Kk; j++) o = fmaf(sattn[h][j], mp[j * Ff], o);
    }
    out[g * Ff + t] = o * (1.f / Hh);
}

// ---------------------------------------------------------------------------

extern "C" void kernel_launch(void* const* d_in, const int* in_sizes, int n_in,
                              void* d_out, int out_size) {
    const float* elem_weights = (const float*)d_in[0];
    const float* elem_fea_in  = (const float*)d_in[1];
    const float* W_init = (const float*)d_in[2];
    const float* b_init = (const float*)d_in[3];
    const float* mg_W1  = (const float*)d_in[4];
    const float* mg_b1  = (const float*)d_in[5];
    const float* mg_W2  = (const float*)d_in[6];
    const float* mg_b2  = (const float*)d_in[7];
    const float* mm_W1  = (const float*)d_in[8];
    const float* mm_b1  = (const float*)d_in[9];
    const float* mm_W2  = (const float*)d_in[10];
    const float* mm_b2  = (const float*)d_in[11];
    const float* m_pow  = (const float*)d_in[12];
    const float* cg_W1  = (const float*)d_in[13];
    const float* cg_b1  = (const float*)d_in[14];
    const float* cg_W2  = (const float*)d_in[15];
    const float* cg_b2  = (const float*)d_in[16];
    const float* cm_W1  = (const float*)d_in[17];
    const float* cm_b1  = (const float*)d_in[18];
    const float* cm_W2  = (const float*)d_in[19];
    const float* cm_b2  = (const float*)d_in[20];
    const float* c_pow  = (const float*)d_in[21];
    // d_in[22] = batch (implicit: n/16), unused
    const int* self_idx = (const int*)d_in[23];
    const int* nbr_idx  = (const int*)d_in[24];
    float* out = (float*)d_out;

    const int EDGE_SMEM = (128 * SP + 256 * SP + 64) * (int)sizeof(float);  // 110848
    const int CRY_SMEM  = (64 * Ff + 64 * HIDd + 64) * (int)sizeof(float);  // 82176
    cudaFuncSetAttribute((const void*)edge_kernel,
                         cudaFuncAttributeMaxDynamicSharedMemorySize, EDGE_SMEM);
    cudaFuncSetAttribute((const void*)cry_node_kernel,
                         cudaFuncAttributeMaxDynamicSharedMemorySize, CRY_SMEM);

    embed_kernel<<<Nn, 64>>>(elem_weights, elem_fea_in, W_init, b_init);

    for (int l = 0; l < Ll; l++) {
        edge_kernel<<<dim3(Ee / 64, Hh), 512, EDGE_SMEM>>>(
            mg_W1, mg_b1, mg_W2, mg_b2, mm_W1, mm_b1, mm_W2, mm_b2,
            self_idx, nbr_idx, l);
        node_agg_kernel<<<Nn, 64>>>(elem_weights, nbr_idx, m_pow, l);
    }

    cry_node_kernel<<<dim3(Nn / 64, Hh), 256, CRY_SMEM>>>(
        cg_W1, cg_b1, cg_W2, cg_b2, cm_W1, cm_b1, cm_W2, cm_b2);
    cry_agg_kernel<<<Gg, 64>>>(elem_weights, c_pow, out);
}

// round 4
// speedup vs baseline: 5.0024x; 4.5067x over previous
#include <cuda_runtime.h>
#include <math.h>

// Problem constants (fixed by setup_inputs)
#define Gg   256
#define Kk   16
#define Ll   3
#define Hh   3
#define Ff   64
#define EMBd 200
#define HIDd 256
#define DEG  15
#define S    260    // padded smem row stride for [16][256] arrays (floats)

typedef unsigned long long u64;

__device__ __forceinline__ float selu_f(float x) {
    const float sc = 1.0507009873554805f;
    const float al = 1.6732632423543772f;
    return x > 0.f ? sc * x : sc * al * (expf(x) - 1.f);
}
__device__ __forceinline__ u64 pack2(float lo, float hi) {
    u64 r; asm("mov.b64 %0, {%1, %2};" : "=l"(r) : "f"(lo), "f"(hi)); return r;
}
__device__ __forceinline__ void unpack2(u64 v, float& a, float& b) {
    asm("mov.b64 {%0, %1}, %2;" : "=f"(a), "=f"(b) : "l"(v));
}
__device__ __forceinline__ u64 fma2(u64 a, u64 b, u64 c) {
    u64 d; asm("fma.rn.f32x2 %0, %1, %2, %3;" : "=l"(d) : "l"(a), "l"(b), "l"(c));
    return d;
}
__device__ __forceinline__ void lds128(u64& p01, u64& p23, unsigned addr) {
    asm volatile("ld.shared.v2.b64 {%0, %1}, [%2];"
                 : "=l"(p01), "=l"(p23) : "r"(addr));
}
__device__ __forceinline__ unsigned sm_u32(const void* p) {
    unsigned r;
    asm("{ .reg .u64 t; cvta.to.shared.u64 t, %1; cvt.u32.u64 %0, t; }"
        : "=r"(r) : "l"(p));
    return r;
}

// Node projections for pair-input nets:
//   A[n][t] = sum_k feaT[k][n] * W1[k][t]      + b1[t]
//   B[n][t] = sum_k feaT[k][n] * W1[64+k][t]
// 256 threads, thread t = hidden column. feaT is [64][16] (broadcast LDS).
__device__ __forceinline__ void proj_pair(const float* __restrict__ sfeaT,
                                          float* __restrict__ A,
                                          float* __restrict__ B,
                                          const float* __restrict__ W1,
                                          const float* __restrict__ b1, int t) {
    u64 aA[8], aB[8];
    const float bv = b1[t];
    const u64 bv2 = pack2(bv, bv);
    const u64 z2  = pack2(0.f, 0.f);
    #pragma unroll
    for (int m = 0; m < 8; m++) { aA[m] = bv2; aB[m] = z2; }
    const unsigned fa = sm_u32(sfeaT);
    #pragma unroll 4
    for (int k = 0; k < Ff; k++) {
        const float ws = W1[k * HIDd + t];
        const float wn = W1[(Ff + k) * HIDd + t];
        const u64 ws2 = pack2(ws, ws);
        const u64 wn2 = pack2(wn, wn);
        u64 f0, f1, f2, f3, f4, f5, f6, f7;
        lds128(f0, f1, fa + (k * 16 + 0) * 4);
        lds128(f2, f3, fa + (k * 16 + 4) * 4);
        lds128(f4, f5, fa + (k * 16 + 8) * 4);
        lds128(f6, f7, fa + (k * 16 + 12) * 4);
        aA[0] = fma2(f0, ws2, aA[0]);  aB[0] = fma2(f0, wn2, aB[0]);
        aA[1] = fma2(f1, ws2, aA[1]);  aB[1] = fma2(f1, wn2, aB[1]);
        aA[2] = fma2(f2, ws2, aA[2]);  aB[2] = fma2(f2, wn2, aB[2]);
        aA[3] = fma2(f3, ws2, aA[3]);  aB[3] = fma2(f3, wn2, aB[3]);
        aA[4] = fma2(f4, ws2, aA[4]);  aB[4] = fma2(f4, wn2, aB[4]);
        aA[5] = fma2(f5, ws2, aA[5]);  aB[5] = fma2(f5, wn2, aB[5]);
        aA[6] = fma2(f6, ws2, aA[6]);  aB[6] = fma2(f6, wn2, aB[6]);
        aA[7] = fma2(f7, ws2, aA[7]);  aB[7] = fma2(f7, wn2, aB[7]);
    }
    #pragma unroll
    for (int m = 0; m < 8; m++) {
        float x, y;
        unpack2(aA[m], x, y);
        A[(2 * m) * S + t] = x;  A[(2 * m + 1) * S + t] = y;
        unpack2(aB[m], x, y);
        B[(2 * m) * S + t] = x;  B[(2 * m + 1) * S + t] = y;
    }
}

// Single projection (cry nets, input dim 64, no B half).
__device__ __forceinline__ void proj_single(const float* __restrict__ sfeaT,
                                            float* __restrict__ A,
                                            const float* __restrict__ W1,
                                            const float* __restrict__ b1, int t) {
    u64 aA[8];
    const float bv = b1[t];
    const u64 bv2 = pack2(bv, bv);
    #pragma unroll
    for (int m = 0; m < 8; m++) aA[m] = bv2;
    const unsigned fa = sm_u32(sfeaT);
    #pragma unroll 4
    for (int k = 0; k < Ff; k++) {
        const float ws = W1[k * HIDd + t];
        const u64 ws2 = pack2(ws, ws);
        u64 f0, f1, f2, f3, f4, f5, f6, f7;
        lds128(f0, f1, fa + (k * 16 + 0) * 4);
        lds128(f2, f3, fa + (k * 16 + 4) * 4);
        lds128(f4, f5, fa + (k * 16 + 8) * 4);
        lds128(f6, f7, fa + (k * 16 + 12) * 4);
        aA[0] = fma2(f0, ws2, aA[0]);
        aA[1] = fma2(f1, ws2, aA[1]);
        aA[2] = fma2(f2, ws2, aA[2]);
        aA[3] = fma2(f3, ws2, aA[3]);
        aA[4] = fma2(f4, ws2, aA[4]);
        aA[5] = fma2(f5, ws2, aA[5]);
        aA[6] = fma2(f6, ws2, aA[6]);
        aA[7] = fma2(f7, ws2, aA[7]);
    }
    #pragma unroll
    for (int m = 0; m < 8; m++) {
        float x, y;
        unpack2(aA[m], x, y);
        A[(2 * m) * S + t] = x;  A[(2 * m + 1) * S + t] = y;
    }
}

// ---------------------------------------------------------------------------
// One block = one graph (16 nodes, 240 edges). Full network fused:
// embed -> 3 message-passing layers (3 heads each) -> cry pooling -> out.
// Key algebra: W1 factored to node projections (hidden[e]=selu(A[i]+B[j])),
// and attention-weighted message sum pulled inside W2:
//   sum_j attn_j*(hid_j@W2 + b) = (sum_j attn_j*hid_j)@W2 + (sum_j attn_j)*b.
// All __syncthreads() are at uniform control flow (no divergent barriers).
// ---------------------------------------------------------------------------
__global__ void __launch_bounds__(256, 2)
fused_kernel(const float* __restrict__ ew, const float* __restrict__ efea,
             const float* __restrict__ Wi, const float* __restrict__ bi,
             const float* __restrict__ gW1, const float* __restrict__ gb1,
             const float* __restrict__ gW2, const float* __restrict__ gb2,
             const float* __restrict__ mW1, const float* __restrict__ mb1,
             const float* __restrict__ mW2, const float* __restrict__ mb2,
             const float* __restrict__ m_pow,
             const float* __restrict__ cgW1, const float* __restrict__ cgb1,
             const float* __restrict__ cgW2, const float* __restrict__ cgb2,
             const float* __restrict__ cmW1, const float* __restrict__ cmb1,
             const float* __restrict__ cmW2, const float* __restrict__ cmb2,
             const float* __restrict__ c_pow,
             float* __restrict__ out) {
    extern __shared__ float sm[];
    float* sfeaT  = sm;                 // [64][16]
    float* sdelta = sm + 1024;          // [16][64]
    float* sA     = sm + 2048;          // [16][S]
    float* sB     = sA + 16 * S;        // [16][S]
    float* sH     = sB + 16 * S;        // [16][S]
    float* sgate  = sH + 16 * S;        // [240]
    float* sattn  = sgate + 240;        // [240]
    float* ssum   = sattn + 240;        // [16]
    float* sw_    = ssum + 16;          // [16]
    float* sout   = sw_ + 16;           // [64]
    float* sred   = sout + 64;          // [4][64]

    const int g = blockIdx.x;
    const int t = threadIdx.x;

    if (t < Kk) sw_[t] = ew[g * Kk + t];

    // ---- embed: stage elem_fea in sA region, compute fea transposed ----
    {
        float* sEmb = sA;  // 3200 floats fits in sA (4160); no alias w/ sfeaT
        for (int idx = t; idx < Kk * EMBd; idx += 256)
            sEmb[idx] = efea[(size_t)g * Kk * EMBd + idx];
        __syncthreads();
        const int f = t & 63, q = t >> 6;  // 4 nodes per thread (q selects)
        if (f < Ff - 1) {
            float a0 = bi[f], a1 = bi[f], a2 = bi[f], a3 = bi[f];
            #pragma unroll 4
            for (int k = 0; k < EMBd; k++) {
                const float wv = Wi[k * (Ff - 1) + f];
                a0 = fmaf(sEmb[(q * 4 + 0) * EMBd + k], wv, a0);
                a1 = fmaf(sEmb[(q * 4 + 1) * EMBd + k], wv, a1);
                a2 = fmaf(sEmb[(q * 4 + 2) * EMBd + k], wv, a2);
                a3 = fmaf(sEmb[(q * 4 + 3) * EMBd + k], wv, a3);
            }
            sfeaT[f * 16 + q * 4 + 0] = a0;
            sfeaT[f * 16 + q * 4 + 1] = a1;
            sfeaT[f * 16 + q * 4 + 2] = a2;
            sfeaT[f * 16 + q * 4 + 3] = a3;
        } else {
            sfeaT[63 * 16 + q * 4 + 0] = sw_[q * 4 + 0];
            sfeaT[63 * 16 + q * 4 + 1] = sw_[q * 4 + 1];
            sfeaT[63 * 16 + q * 4 + 2] = sw_[q * 4 + 2];
            sfeaT[63 * 16 + q * 4 + 3] = sw_[q * 4 + 3];
        }
        __syncthreads();
    }

    // ---- message passing layers ----
    for (int l = 0; l < Ll; l++) {
        for (int idx = t; idx < Kk * Ff; idx += 256) sdelta[idx] = 0.f;
        __syncthreads();

        for (int h = 0; h < Hh; h++) {
            const int lh = l * Hh + h;

            // gate projections
            proj_pair(sfeaT, sA, sB, gW1 + (size_t)lh * 2 * Ff * HIDd,
                      gb1 + lh * HIDd, t);
            __syncthreads();

            // gate per edge: gate[e] = sum_t selu(A[i,t]+B[j,t])*gW2[t] + gb2
            if (t < 240) {
                const int i = t / DEG, jj = t - i * DEG;
                const int j = jj + (jj >= i);
                const float* w2p = gW2 + lh * HIDd;
                float acc = 0.f;
                #pragma unroll 4
                for (int tt = 0; tt < HIDd; tt += 4) {
                    const float4 a = *(const float4*)&sA[i * S + tt];
                    const float4 b = *(const float4*)&sB[j * S + tt];
                    const float4 w = *(const float4*)&w2p[tt];
                    acc = fmaf(selu_f(a.x + b.x), w.x, acc);
                    acc = fmaf(selu_f(a.y + b.y), w.y, acc);
                    acc = fmaf(selu_f(a.z + b.z), w.z, acc);
                    acc = fmaf(selu_f(a.w + b.w), w.w, acc);
                }
                sgate[t] = acc + gb2[lh];
            }
            __syncthreads();

            // segment softmax per node (weighted by wn^pow)
            if (t < Kk) {
                const int i = t;
                const float pw = m_pow[lh];
                float gv[DEG];
                float gmax = -1e30f;
                #pragma unroll
                for (int jj = 0; jj < DEG; jj++) {
                    gv[jj] = sgate[i * DEG + jj];
                    gmax = fmaxf(gmax, gv[jj]);
                }
                float den = 1e-10f;
                #pragma unroll
                for (int jj = 0; jj < DEG; jj++) {
                    const int j = jj + (jj >= i);
                    const float a = powf(sw_[j], pw) * expf(gv[jj] - gmax);
                    sattn[i * DEG + jj] = a;
                    den += a;
                }
                const float inv = 1.f / den;
                #pragma unroll
                for (int jj = 0; jj < DEG; jj++) sattn[i * DEG + jj] *= inv;
                ssum[i] = (den - 1e-10f) * inv;  // sum of attn (for bias)
            }
            __syncthreads();

            // msg projections (overwrite sA/sB)
            proj_pair(sfeaT, sA, sB, mW1 + (size_t)lh * 2 * Ff * HIDd,
                      mb1 + lh * HIDd, t);
            __syncthreads();

            // H[i,t] = sum_j attn[i,j]*selu(mA[i,t]+mB[j,t])
            {
                const int i = t >> 4, tc = (t & 15) * 16;
                float va[16], hq[16];
                #pragma unroll
                for (int u = 0; u < 16; u++) {
                    va[u] = sA[i * S + tc + u];
                    hq[u] = 0.f;
                }
                #pragma unroll 1
                for (int jj = 0; jj < DEG; jj++) {
                    const int j = jj + (jj >= i);
                    const float a = sattn[i * DEG + jj];
                    const float* bp = &sB[j * S + tc];
                    #pragma unroll
                    for (int u = 0; u < 16; u++)
                        hq[u] = fmaf(a, selu_f(va[u] + bp[u]), hq[u]);
                }
                #pragma unroll
                for (int u = 0; u < 16; u++) sH[i * S + tc + u] = hq[u];
            }
            __syncthreads();

            // delta[i,f] += H[i,:] @ W2[:,f] + ssum[i]*mb2[f]
            {
                const int i = t >> 4, fb = (t & 15) * 4;
                const float* W2 = mW2 + (size_t)lh * HIDd * Ff;
                const float* b2 = mb2 + lh * Ff;
                const float si = ssum[i];
                float a0 = si * b2[fb + 0], a1 = si * b2[fb + 1];
                float a2 = si * b2[fb + 2], a3 = si * b2[fb + 3];
                #pragma unroll 4
                for (int tt = 0; tt < HIDd; tt++) {
                    const float hv = sH[i * S + tt];
                    const float4 w = *(const float4*)&W2[tt * Ff + fb];
                    a0 = fmaf(hv, w.x, a0);
                    a1 = fmaf(hv, w.y, a1);
                    a2 = fmaf(hv, w.z, a2);
                    a3 = fmaf(hv, w.w, a3);
                }
                sdelta[i * Ff + fb + 0] += a0;
                sdelta[i * Ff + fb + 1] += a1;
                sdelta[i * Ff + fb + 2] += a2;
                sdelta[i * Ff + fb + 3] += a3;
            }
            __syncthreads();
        }

        // residual: fea += mean over heads
        for (int idx = t; idx < Kk * Ff; idx += 256) {
            const int i = idx >> 6, f = idx & 63;
            sfeaT[f * 16 + i] += sdelta[idx] * (1.f / Hh);
        }
        __syncthreads();
    }

    // ---- cry pooling ----
    if (t < Ff) sout[t] = 0.f;
    __syncthreads();

    for (int h = 0; h < Hh; h++) {
        // gate proj
        proj_single(sfeaT, sA, cgW1 + (size_t)h * Ff * HIDd, cgb1 + h * HIDd, t);
        __syncthreads();
        // node gate: partial dot over 16 hidden, reduce across 16 lanes
        {
            const int n = t >> 4, tc = (t & 15) * 16;
            const float* w2p = cgW2 + h * HIDd;
            float p = 0.f;
            #pragma unroll
            for (int u = 0; u < 16; u++)
                p = fmaf(selu_f(sA[n * S + tc + u]), w2p[tc + u], p);
            #pragma unroll
            for (int o = 8; o; o >>= 1) p += __shfl_xor_sync(0xffffffffu, p, o);
            if ((t & 15) == 0) sgate[n] = p + cgb2[h];
        }
        __syncthreads();
        // softmax over the 16 nodes
        if (t == 0) {
            const float pw = c_pow[h];
            float gmax = -1e30f;
            #pragma unroll
            for (int n = 0; n < Kk; n++) gmax = fmaxf(gmax, sgate[n]);
            float den = 1e-10f;
            #pragma unroll
            for (int n = 0; n < Kk; n++) {
                const float a = powf(sw_[n], pw) * expf(sgate[n] - gmax);
                sattn[n] = a;
                den += a;
            }
            const float inv = 1.f / den;
            #pragma unroll
            for (int n = 0; n < Kk; n++) sattn[n] *= inv;
            ssum[0] = (den - 1e-10f) * inv;
        }
        __syncthreads();
        // msg proj
        proj_single(sfeaT, sA, cmW1 + (size_t)h * Ff * HIDd, cmb1 + h * HIDd, t);
        __syncthreads();
        // Hc[t] = sum_n attn[n]*selu(mA[n,t])
        {
            float hc = 0.f;
            #pragma unroll
            for (int n = 0; n < Kk; n++)
                hc = fmaf(sattn[n], selu_f(sA[n * S + t]), hc);
            sH[t] = hc;
        }
        __syncthreads();
        // out[f] += Hc @ cmW2[:,f] + ssum*cmb2[f]; split 256 hidden over 4 groups
        {
            const int f = t & 63, qt = t >> 6;
            const float* W2 = cmW2 + (size_t)h * HIDd * Ff;
            float p = 0.f;
            #pragma unroll 4
            for (int tt = qt * 64; tt < qt * 64 + 64; tt++)
                p = fmaf(sH[tt], W2[tt * Ff + f], p);
            sred[qt * 64 + f] = p;
        }
        __syncthreads();
        if (t < Ff) {
            sout[t] += sred[t] + sred[64 + t] + sred[128 + t] + sred[192 + t]
                     + ssum[0] * cmb2[h * Ff + t];
        }
        __syncthreads();
    }

    if (t < Ff) out[g * Ff + t] = sout[t] * (1.f / Hh);
}

// ---------------------------------------------------------------------------

extern "C" void kernel_launch(void* const* d_in, const int* in_sizes, int n_in,
                              void* d_out, int out_size) {
    const float* elem_weights = (const float*)d_in[0];
    const float* elem_fea_in  = (const float*)d_in[1];
    const float* W_init = (const float*)d_in[2];
    const float* b_init = (const float*)d_in[3];
    const float* mg_W1  = (const float*)d_in[4];
    const float* mg_b1  = (const float*)d_in[5];
    const float* mg_W2  = (const float*)d_in[6];
    const float* mg_b2  = (const float*)d_in[7];
    const float* mm_W1  = (const float*)d_in[8];
    const float* mm_b1  = (const float*)d_in[9];
    const float* mm_W2  = (const float*)d_in[10];
    const float* mm_b2  = (const float*)d_in[11];
    const float* m_pow  = (const float*)d_in[12];
    const float* cg_W1  = (const float*)d_in[13];
    const float* cg_b1  = (const float*)d_in[14];
    const float* cg_W2  = (const float*)d_in[15];
    const float* cg_b2  = (const float*)d_in[16];
    const float* cm_W1  = (const float*)d_in[17];
    const float* cm_b1  = (const float*)d_in[18];
    const float* cm_W2  = (const float*)d_in[19];
    const float* cm_b2  = (const float*)d_in[20];
    const float* c_pow  = (const float*)d_in[21];
    // d_in[22] = batch, d_in[23] = self_idx, d_in[24] = nbr_idx: implicit
    float* out = (float*)d_out;

    const int SMEM = (1024 + 1024 + 3 * 16 * S + 240 + 240 + 16 + 16 + 64 + 256)
                     * (int)sizeof(float);  // 61440 B
    cudaFuncSetAttribute((const void*)fused_kernel,
                         cudaFuncAttributeMaxDynamicSharedMemorySize, SMEM);

    fused_kernel<<<Gg, 256, SMEM>>>(
        elem_weights, elem_fea_in, W_init, b_init,
        mg_W1, mg_b1, mg_W2, mg_b2, mm_W1, mm_b1, mm_W2, mm_b2, m_pow,
        cg_W1, cg_b1, cg_W2, cg_b2, cm_W1, cm_b1, cm_W2, cm_b2, c_pow,
        out);
}

// round 5
// speedup vs baseline: 6.0944x; 1.2183x over previous
#include <cuda_runtime.h>
#include <math.h>

// Problem constants (fixed by setup_inputs)
#define Gg   256
#define Kk   16
#define Ll   3
#define Hh   3
#define Ff   64
#define EMBd 200
#define HIDd 256
#define DEG  15
#define S    260    // padded smem row stride for [16][256] arrays (floats)

typedef unsigned long long u64;

__device__ __forceinline__ float selu_f(float x) {
    // scale = 1.0507009873554805, scale*alpha = 1.7580993408473766
    return x > 0.f ? 1.0507009873554805f * x
                   : 1.7580993408473766f * (__expf(x) - 1.f);
}
__device__ __forceinline__ u64 pack2(float lo, float hi) {
    u64 r; asm("mov.b64 %0, {%1, %2};" : "=l"(r) : "f"(lo), "f"(hi)); return r;
}
__device__ __forceinline__ void unpack2(u64 v, float& a, float& b) {
    asm("mov.b64 {%0, %1}, %2;" : "=f"(a), "=f"(b) : "l"(v));
}
__device__ __forceinline__ u64 fma2(u64 a, u64 b, u64 c) {
    u64 d; asm("fma.rn.f32x2 %0, %1, %2, %3;" : "=l"(d) : "l"(a), "l"(b), "l"(c));
    return d;
}
__device__ __forceinline__ void lds128(u64& p01, u64& p23, unsigned addr) {
    asm volatile("ld.shared.v2.b64 {%0, %1}, [%2];"
                 : "=l"(p01), "=l"(p23) : "r"(addr));
}
__device__ __forceinline__ unsigned sm_u32(const void* p) {
    unsigned r;
    asm("{ .reg .u64 t; cvta.to.shared.u64 t, %1; cvt.u32.u64 %0, t; }"
        : "=r"(r) : "l"(p));
    return r;
}

// One pass of a [16 x 64] @ [64 x 256] projection: 8 u64 accumulators only
// (keeps live regs under the 64-reg budget for 512thr x 2CTA occupancy).
// u = hidden column (0..255). feaT is [64][16], broadcast LDS reads.
__device__ __forceinline__ void proj_pass(const float* __restrict__ sfeaT,
                                          float* __restrict__ Dst,
                                          const float* __restrict__ W1,
                                          float bias, int u) {
    u64 acc[8];
    const u64 bv2 = pack2(bias, bias);
    #pragma unroll
    for (int m = 0; m < 8; m++) acc[m] = bv2;
    const unsigned fa = sm_u32(sfeaT);
    #pragma unroll 4
    for (int k = 0; k < Ff; k++) {
        const float w = W1[k * HIDd + u];
        const u64 w2 = pack2(w, w);
        u64 f0, f1, f2, f3, f4, f5, f6, f7;
        lds128(f0, f1, fa + (k * 16 + 0) * 4);
        lds128(f2, f3, fa + (k * 16 + 4) * 4);
        lds128(f4, f5, fa + (k * 16 + 8) * 4);
        lds128(f6, f7, fa + (k * 16 + 12) * 4);
        acc[0] = fma2(f0, w2, acc[0]);
        acc[1] = fma2(f1, w2, acc[1]);
        acc[2] = fma2(f2, w2, acc[2]);
        acc[3] = fma2(f3, w2, acc[3]);
        acc[4] = fma2(f4, w2, acc[4]);
        acc[5] = fma2(f5, w2, acc[5]);
        acc[6] = fma2(f6, w2, acc[6]);
        acc[7] = fma2(f7, w2, acc[7]);
    }
    #pragma unroll
    for (int m = 0; m < 8; m++) {
        float x, y;
        unpack2(acc[m], x, y);
        Dst[(2 * m) * S + u] = x;
        Dst[(2 * m + 1) * S + u] = y;
    }
}

// Pair projection = two passes (A: W1 rows 0..63 with bias, B: rows 64..127).
__device__ __forceinline__ void proj_ab(const float* __restrict__ sfeaT,
                                        float* __restrict__ A,
                                        float* __restrict__ B,
                                        const float* __restrict__ W1,
                                        const float* __restrict__ b1, int u) {
    proj_pass(sfeaT, A, W1, b1[u], u);
    proj_pass(sfeaT, B, W1 + Ff * HIDd, 0.f, u);
}

// ---------------------------------------------------------------------------
// One block = one graph. 512 threads: during projections, threads 0-255 run
// the gate net while 256-511 run the msg net concurrently (independent).
// Full network fused: embed -> 3 layers x 3 heads -> cry pooling -> out.
// Algebra: W1 factored to node projections (hidden[e]=selu(A[i]+B[j]));
// attention pulled through W2: sum_j a_j*(h_j@W2+b) = (sum_j a_j*h_j)@W2
// + (sum_j a_j)*b.  All barriers at uniform control flow.
// ---------------------------------------------------------------------------
__global__ void __launch_bounds__(512, 2)
fused_kernel(const float* __restrict__ ew, const float* __restrict__ efea,
             const float* __restrict__ Wi, const float* __restrict__ bi,
             const float* __restrict__ gW1, const float* __restrict__ gb1,
             const float* __restrict__ gW2, const float* __restrict__ gb2,
             const float* __restrict__ mW1, const float* __restrict__ mb1,
             const float* __restrict__ mW2, const float* __restrict__ mb2,
             const float* __restrict__ m_pow,
             const float* __restrict__ cgW1, const float* __restrict__ cgb1,
             const float* __restrict__ cgW2, const float* __restrict__ cgb2,
             const float* __restrict__ cmW1, const float* __restrict__ cmb1,
             const float* __restrict__ cmW2, const float* __restrict__ cmb2,
             const float* __restrict__ c_pow,
             float* __restrict__ out) {
    extern __shared__ float sm[];
    float* sfeaT  = sm;                 // [64][16]
    float* sdelta = sm + 1024;          // [16][64]
    float* sAg    = sm + 2048;          // [16][S]  gate A  (reused as sH)
    float* sBg    = sAg + 16 * S;       // [16][S]  gate B  (reused as Hc)
    float* sAm    = sBg + 16 * S;       // [16][S]  msg A
    float* sBm    = sAm + 16 * S;       // [16][S]  msg B
    float* sgate  = sBm + 16 * S;       // [240]
    float* sattn  = sgate + 240;        // [240]
    float* ssum   = sattn + 240;        // [16]
    float* sw_    = ssum + 16;          // [16]
    float* sout   = sw_ + 16;           // [64]
    float* sred   = sout + 64;          // [8][64]
    float* sH     = sAg;                // alias: gate A dead after softmax
    float* sHc    = sBg;                // alias for cry pooled hidden

    const int g = blockIdx.x;
    const int t = threadIdx.x;

    if (t < Kk) sw_[t] = ew[g * Kk + t];

    // ---- embed: stage elem_fea in sAg region, compute fea transposed ----
    {
        float* sEmb = sAg;  // 3200 floats fits in sAg (4160)
        for (int idx = t; idx < Kk * EMBd; idx += 512)
            sEmb[idx] = efea[(size_t)g * Kk * EMBd + idx];
        __syncthreads();
        const int f = t & 63, q = t >> 6;  // q = 0..7, nodes 2q and 2q+1
        if (f < Ff - 1) {
            float a0 = bi[f], a1 = bi[f];
            #pragma unroll 4
            for (int k = 0; k < EMBd; k++) {
                const float wv = Wi[k * (Ff - 1) + f];
                a0 = fmaf(sEmb[(2 * q) * EMBd + k], wv, a0);
                a1 = fmaf(sEmb[(2 * q + 1) * EMBd + k], wv, a1);
            }
            sfeaT[f * 16 + 2 * q]     = a0;
            sfeaT[f * 16 + 2 * q + 1] = a1;
        } else {
            sfeaT[63 * 16 + 2 * q]     = sw_[2 * q];
            sfeaT[63 * 16 + 2 * q + 1] = sw_[2 * q + 1];
        }
        __syncthreads();
    }

    // ---- message passing layers ----
    for (int l = 0; l < Ll; l++) {
        for (int idx = t; idx < Kk * Ff; idx += 512) sdelta[idx] = 0.f;
        __syncthreads();

        for (int h = 0; h < Hh; h++) {
            const int lh = l * Hh + h;

            // gate (threads 0-255) and msg (256-511) projections in parallel
            if (t < 256)
                proj_ab(sfeaT, sAg, sBg, gW1 + (size_t)lh * 2 * Ff * HIDd,
                        gb1 + lh * HIDd, t);
            else
                proj_ab(sfeaT, sAm, sBm, mW1 + (size_t)lh * 2 * Ff * HIDd,
                        mb1 + lh * HIDd, t - 256);
            __syncthreads();

            // gate per edge: 2 threads per edge (halves of the 256-dot)
            if (t < 480) {
                const int e = t >> 1, half = t & 1;
                const int i = e / DEG, jj = e - i * DEG;
                const int j = jj + (jj >= i);
                const float* w2p = gW2 + lh * HIDd + half * 128;
                const float* ap = &sAg[i * S + half * 128];
                const float* bp = &sBg[j * S + half * 128];
                float acc = 0.f;
                #pragma unroll 8
                for (int tt = 0; tt < 128; tt += 4) {
                    const float4 a = *(const float4*)&ap[tt];
                    const float4 b = *(const float4*)&bp[tt];
                    const float4 w = *(const float4*)&w2p[tt];
                    acc = fmaf(selu_f(a.x + b.x), w.x, acc);
                    acc = fmaf(selu_f(a.y + b.y), w.y, acc);
                    acc = fmaf(selu_f(a.z + b.z), w.z, acc);
                    acc = fmaf(selu_f(a.w + b.w), w.w, acc);
                }
                acc += __shfl_xor_sync(0xffffffffu, acc, 1);
                if (half == 0) sgate[e] = acc + gb2[lh];
            }
            __syncthreads();

            // segment softmax per node (weighted by wn^pow)
            if (t < Kk) {
                const int i = t;
                const float pw = m_pow[lh];
                float gv[DEG];
                float gmax = -1e30f;
                #pragma unroll
                for (int jj = 0; jj < DEG; jj++) {
                    gv[jj] = sgate[i * DEG + jj];
                    gmax = fmaxf(gmax, gv[jj]);
                }
                float den = 1e-10f;
                #pragma unroll
                for (int jj = 0; jj < DEG; jj++) {
                    const int j = jj + (jj >= i);
                    const float a = powf(sw_[j], pw) * expf(gv[jj] - gmax);
                    sattn[i * DEG + jj] = a;
                    den += a;
                }
                const float inv = 1.f / den;
                #pragma unroll
                for (int jj = 0; jj < DEG; jj++) sattn[i * DEG + jj] *= inv;
                ssum[i] = (den - 1e-10f) * inv;  // sum of attn (for bias)
            }
            __syncthreads();

            // H[i,c] = sum_j attn[i,j]*selu(mA[i,c]+mB[j,c]); 512 thr, 8 cols
            {
                const int i = t >> 5, lane = t & 31;
                const int c0 = lane * 4, c1 = 128 + lane * 4;
                const float4 va0 = *(const float4*)&sAm[i * S + c0];
                const float4 va1 = *(const float4*)&sAm[i * S + c1];
                float4 h0 = make_float4(0.f, 0.f, 0.f, 0.f);
                float4 h1 = make_float4(0.f, 0.f, 0.f, 0.f);
                #pragma unroll 1
                for (int jj = 0; jj < DEG; jj++) {
                    const int j = jj + (jj >= i);
                    const float a = sattn[i * DEG + jj];
                    const float4 b0 = *(const float4*)&sBm[j * S + c0];
                    const float4 b1v = *(const float4*)&sBm[j * S + c1];
                    h0.x = fmaf(a, selu_f(va0.x + b0.x), h0.x);
                    h0.y = fmaf(a, selu_f(va0.y + b0.y), h0.y);
                    h0.z = fmaf(a, selu_f(va0.z + b0.z), h0.z);
                    h0.w = fmaf(a, selu_f(va0.w + b0.w), h0.w);
                    h1.x = fmaf(a, selu_f(va1.x + b1v.x), h1.x);
                    h1.y = fmaf(a, selu_f(va1.y + b1v.y), h1.y);
                    h1.z = fmaf(a, selu_f(va1.z + b1v.z), h1.z);
                    h1.w = fmaf(a, selu_f(va1.w + b1v.w), h1.w);
                }
                *(float4*)&sH[i * S + c0] = h0;
                *(float4*)&sH[i * S + c1] = h1;
            }
            __syncthreads();

            // delta[i,f] += H[i,:] @ W2[:,f] + ssum[i]*mb2[f]; 512 thr, 2 f
            {
                const int i = t >> 5, fb = (t & 31) * 2;
                const float* W2 = mW2 + (size_t)lh * HIDd * Ff;
                const float* b2 = mb2 + lh * Ff;
                const float si = ssum[i];
                float a0 = si * b2[fb], a1 = si * b2[fb + 1];
                #pragma unroll 4
                for (int tt = 0; tt < HIDd; tt++) {
                    const float hv = sH[i * S + tt];
                    const float2 w = *(const float2*)&W2[tt * Ff + fb];
                    a0 = fmaf(hv, w.x, a0);
                    a1 = fmaf(hv, w.y, a1);
                }
                sdelta[i * Ff + fb]     += a0;
                sdelta[i * Ff + fb + 1] += a1;
            }
            __syncthreads();
        }

        // residual: fea += mean over heads
        for (int idx = t; idx < Kk * Ff; idx += 512) {
            const int i = idx >> 6, f = idx & 63;
            sfeaT[f * 16 + i] += sdelta[idx] * (1.f / Hh);
        }
        __syncthreads();
    }

    // ---- cry pooling ----
    if (t < Ff) sout[t] = 0.f;
    __syncthreads();

    for (int h = 0; h < Hh; h++) {
        // gate proj (0-255) and msg proj (256-511) in parallel
        if (t < 256)
            proj_pass(sfeaT, sAg, cgW1 + (size_t)h * Ff * HIDd,
                      cgb1[h * HIDd + t], t);
        else
            proj_pass(sfeaT, sAm, cmW1 + (size_t)h * Ff * HIDd,
                      cmb1[h * HIDd + (t - 256)], t - 256);
        __syncthreads();

        // node gate: full-warp dot (32 lanes x 8 cols), warp reduce
        {
            const int n = t >> 5, lane = t & 31;
            const float* w2p = cgW2 + h * HIDd;
            const int c0 = lane * 4, c1 = 128 + lane * 4;
            const float4 a0 = *(const float4*)&sAg[n * S + c0];
            const float4 a1 = *(const float4*)&sAg[n * S + c1];
            const float4 w0 = *(const float4*)&w2p[c0];
            const float4 w1 = *(const float4*)&w2p[c1];
            float p = 0.f;
            p = fmaf(selu_f(a0.x), w0.x, p);
            p = fmaf(selu_f(a0.y), w0.y, p);
            p = fmaf(selu_f(a0.z), w0.z, p);
            p = fmaf(selu_f(a0.w), w0.w, p);
            p = fmaf(selu_f(a1.x), w1.x, p);
            p = fmaf(selu_f(a1.y), w1.y, p);
            p = fmaf(selu_f(a1.z), w1.z, p);
            p = fmaf(selu_f(a1.w), w1.w, p);
            #pragma unroll
            for (int o = 16; o; o >>= 1) p += __shfl_xor_sync(0xffffffffu, p, o);
            if (lane == 0) sgate[n] = p + cgb2[h];
        }
        __syncthreads();

        // softmax over the 16 nodes
        if (t == 0) {
            const float pw = c_pow[h];
            float gmax = -1e30f;
            #pragma unroll
            for (int n = 0; n < Kk; n++) gmax = fmaxf(gmax, sgate[n]);
            float den = 1e-10f;
            #pragma unroll
            for (int n = 0; n < Kk; n++) {
                const float a = powf(sw_[n], pw) * expf(sgate[n] - gmax);
                sattn[n] = a;
                den += a;
            }
            const float inv = 1.f / den;
            #pragma unroll
            for (int n = 0; n < Kk; n++) sattn[n] *= inv;
            ssum[0] = (den - 1e-10f) * inv;
        }
        __syncthreads();

        // Hc[c] = sum_n attn[n]*selu(mA[n,c])   (256 threads)
        if (t < HIDd) {
            float hc = 0.f;
            #pragma unroll
            for (int n = 0; n < Kk; n++)
                hc = fmaf(sattn[n], selu_f(sAm[n * S + t]), hc);
            sHc[t] = hc;
        }
        __syncthreads();

        // out[f] += Hc @ cmW2[:,f] + ssum*cmb2[f]; 8 groups of 32 tt
        {
            const int f = t & 63, qt = t >> 6;
            const float* W2 = cmW2 + (size_t)h * HIDd * Ff;
            float p = 0.f;
            #pragma unroll 4
            for (int tt = qt * 32; tt < qt * 32 + 32; tt++)
                p = fmaf(sHc[tt], W2[tt * Ff + f], p);
            sred[qt * 64 + f] = p;
        }
        __syncthreads();
        if (t < Ff) {
            float s = ssum[0] * cmb2[h * Ff + t];
            #pragma unroll
            for (int q = 0; q < 8; q++) s += sred[q * 64 + t];
            sout[t] += s;
        }
        __syncthreads();
    }

    if (t < Ff) out[g * Ff + t] = sout[t] * (1.f / Hh);
}

// ---------------------------------------------------------------------------

extern "C" void kernel_launch(void* const* d_in, const int* in_sizes, int n_in,
                              void* d_out, int out_size) {
    const float* elem_weights = (const float*)d_in[0];
    const float* elem_fea_in  = (const float*)d_in[1];
    const float* W_init = (const float*)d_in[2];
    const float* b_init = (const float*)d_in[3];
    const float* mg_W1  = (const float*)d_in[4];
    const float* mg_b1  = (const float*)d_in[5];
    const float* mg_W2  = (const float*)d_in[6];
    const float* mg_b2  = (const float*)d_in[7];
    const float* mm_W1  = (const float*)d_in[8];
    const float* mm_b1  = (const float*)d_in[9];
    const float* mm_W2  = (const float*)d_in[10];
    const float* mm_b2  = (const float*)d_in[11];
    const float* m_pow  = (const float*)d_in[12];
    const float* cg_W1  = (const float*)d_in[13];
    const float* cg_b1  = (const float*)d_in[14];
    const float* cg_W2  = (const float*)d_in[15];
    const float* cg_b2  = (const float*)d_in[16];
    const float* cm_W1  = (const float*)d_in[17];
    const float* cm_b1  = (const float*)d_in[18];
    const float* cm_W2  = (const float*)d_in[19];
    const float* cm_b2  = (const float*)d_in[20];
    const float* c_pow  = (const float*)d_in[21];
    // d_in[22] = batch, d_in[23] = self_idx, d_in[24] = nbr_idx: implicit
    float* out = (float*)d_out;

    const int SMEM = (1024 + 1024 + 4 * 16 * S + 240 + 240 + 16 + 16 + 64 + 512)
                     * (int)sizeof(float);  // 79104 B
    cudaFuncSetAttribute((const void*)fused_kernel,
                         cudaFuncAttributeMaxDynamicSharedMemorySize, SMEM);

    fused_kernel<<<Gg, 512, SMEM>>>(
        elem_weights, elem_fea_in, W_init, b_init,
        mg_W1, mg_b1, mg_W2, mg_b2, mm_W1, mm_b1, mm_W2, mm_b2, m_pow,
        cg_W1, cg_b1, cg_W2, cg_b2, cm_W1, cm_b1, cm_W2, cm_b2, c_pow,
        out);
}

// round 7
// speedup vs baseline: 7.0317x; 1.1538x over previous
#include <cuda_runtime.h>
#include <math.h>

// Problem constants (fixed by setup_inputs)
#define Gg   256
#define Kk   16
#define Ll   3
#define Hh   3
#define Ff   64
#define EMBd 200
#define HIDd 256
#define DEG  15
#define S    260    // padded smem row stride (floats); row start 16B-aligned

typedef unsigned long long u64;

__device__ __forceinline__ u64 pack2(float lo, float hi) {
    u64 r; asm("mov.b64 %0, {%1, %2};" : "=l"(r) : "f"(lo), "f"(hi)); return r;
}
__device__ __forceinline__ void unpack2(u64 v, float& a, float& b) {
    asm("mov.b64 {%0, %1}, %2;" : "=f"(a), "=f"(b) : "l"(v));
}
__device__ __forceinline__ u64 fma2(u64 a, u64 b, u64 c) {
    u64 d; asm("fma.rn.f32x2 %0, %1, %2, %3;" : "=l"(d) : "l"(a), "l"(b), "l"(c));
    return d;
}
__device__ __forceinline__ u64 mul2(u64 a, u64 b) {
    u64 d; asm("mul.rn.f32x2 %0, %1, %2;" : "=l"(d) : "l"(a), "l"(b)); return d;
}
__device__ __forceinline__ u64 add2(u64 a, u64 b) {
    u64 d; asm("add.rn.f32x2 %0, %1, %2;" : "=l"(d) : "l"(a), "l"(b)); return d;
}
__device__ __forceinline__ void lds128(u64& p01, u64& p23, unsigned addr) {
    asm volatile("ld.shared.v2.b64 {%0, %1}, [%2];"
                 : "=l"(p01), "=l"(p23) : "r"(addr));
}
__device__ __forceinline__ void sts128(unsigned addr, u64 p01, u64 p23) {
    asm volatile("st.shared.v2.b64 [%0], {%1, %2};"
                 :: "r"(addr), "l"(p01), "l"(p23));
}
__device__ __forceinline__ unsigned sm_u32(const void* p) {
    unsigned r;
    asm("{ .reg .u64 t; cvta.to.shared.u64 t, %1; cvt.u32.u64 %0, t; }"
        : "=r"(r) : "l"(p));
    return r;
}

#define SELU_SC 1.0507009873554805f
#define SELU_SA 1.7580993408473766f

__device__ __forceinline__ float selu_f(float x) {
    return x > 0.f ? SELU_SC * x : SELU_SA * (__expf(x) - 1.f);
}

// Packed selu on a f32x2 pair (pack/unpack movs are register-renames in SASS).
__device__ __forceinline__ u64 selu2(u64 x2) {
    float x0, x1; unpack2(x2, x0, x1);
    const float e0 = __expf(x0), e1 = __expf(x1);
    const u64 n2 = fma2(pack2(e0, e1),
                        pack2(SELU_SA, SELU_SA),
                        pack2(-SELU_SA, -SELU_SA));
    const u64 p2 = mul2(x2, pack2(SELU_SC, SELU_SC));
    float n0, n1, p0, p1;
    unpack2(n2, n0, n1);
    unpack2(p2, p0, p1);
    return pack2(x0 > 0.f ? p0 : n0, x1 > 0.f ? p1 : n1);
}

// One pass of a [16 x 64] @ [64 x 256] projection. u = hidden col (0..255).
__device__ __forceinline__ void proj_pass(const float* __restrict__ sfeaT,
                                          float* __restrict__ Dst,
                                          const float* __restrict__ W1,
                                          float bias, int u) {
    u64 acc[8];
    const u64 bv2 = pack2(bias, bias);
    #pragma unroll
    for (int m = 0; m < 8; m++) acc[m] = bv2;
    const unsigned fa = sm_u32(sfeaT);
    #pragma unroll 4
    for (int k = 0; k < Ff; k++) {
        const float w = W1[k * HIDd + u];
        const u64 w2 = pack2(w, w);
        u64 f0, f1, f2, f3, f4, f5, f6, f7;
        lds128(f0, f1, fa + (k * 16 + 0) * 4);
        lds128(f2, f3, fa + (k * 16 + 4) * 4);
        lds128(f4, f5, fa + (k * 16 + 8) * 4);
        lds128(f6, f7, fa + (k * 16 + 12) * 4);
        acc[0] = fma2(f0, w2, acc[0]);
        acc[1] = fma2(f1, w2, acc[1]);
        acc[2] = fma2(f2, w2, acc[2]);
        acc[3] = fma2(f3, w2, acc[3]);
        acc[4] = fma2(f4, w2, acc[4]);
        acc[5] = fma2(f5, w2, acc[5]);
        acc[6] = fma2(f6, w2, acc[6]);
        acc[7] = fma2(f7, w2, acc[7]);
    }
    #pragma unroll
    for (int m = 0; m < 8; m++) {
        float x, y;
        unpack2(acc[m], x, y);
        Dst[(2 * m) * S + u] = x;
        Dst[(2 * m + 1) * S + u] = y;
    }
}

__device__ __forceinline__ void proj_ab(const float* __restrict__ sfeaT,
                                        float* __restrict__ A,
                                        float* __restrict__ B,
                                        const float* __restrict__ W1,
                                        const float* __restrict__ b1, int u) {
    proj_pass(sfeaT, A, W1, b1[u], u);
    proj_pass(sfeaT, B, W1 + Ff * HIDd, 0.f, u);
}

__device__ __forceinline__ float shxor(float v, int o) {
    return __shfl_xor_sync(0xffffffffu, v, o);
}

// ---------------------------------------------------------------------------
// One block = one graph. 512 threads. Per head: [parallel gate/msg proj] ->
// barrier -> [warp-per-node: gate dots, in-warp softmax (log-weight trick),
// H accumulation, all register/shuffle local] -> barrier -> [W2] -> barrier.
// ---------------------------------------------------------------------------
__global__ void __launch_bounds__(512, 2)
fused_kernel(const float* __restrict__ ew, const float* __restrict__ efea,
             const float* __restrict__ Wi, const float* __restrict__ bi,
             const float* __restrict__ gW1, const float* __restrict__ gb1,
             const float* __restrict__ gW2, const float* __restrict__ gb2,
             const float* __restrict__ mW1, const float* __restrict__ mb1,
             const float* __restrict__ mW2, const float* __restrict__ mb2,
             const float* __restrict__ m_pow,
             const float* __restrict__ cgW1, const float* __restrict__ cgb1,
             const float* __restrict__ cgW2, const float* __restrict__ cgb2,
             const float* __restrict__ cmW1, const float* __restrict__ cmb1,
             const float* __restrict__ cmW2, const float* __restrict__ cmb2,
             const float* __restrict__ c_pow,
             float* __restrict__ out) {
    extern __shared__ float sm[];
    float* sfeaT  = sm;                 // [64][16]
    float* sdelta = sm + 1024;          // [16][64]
    float* sAg    = sm + 2048;          // [16][S] gate A (aliased as sH)
    float* sBg    = sAg + 16 * S;       // [16][S] gate B (aliased as sHc)
    float* sAm    = sBg + 16 * S;       // [16][S] msg A
    float* sBm    = sAm + 16 * S;       // [16][S] msg B
    float* ssum   = sBm + 16 * S;       // [16]
    float* sw_    = ssum + 16;          // [16]
    float* slog   = sw_ + 16;           // [16]  log2(weights)
    float* sgc    = slog + 16;          // [16]  cry gates
    float* sac    = sgc + 16;           // [16]  cry attn
    float* sout   = sac + 16;           // [64]
    float* sred   = sout + 64;          // [8][64]
    float* sH     = sAg;                // alias (row i reused by warp i only)
    float* sHc    = sBg;                // alias

    const int g = blockIdx.x;
    const int t = threadIdx.x;
    const int wid = t >> 5, lane = t & 31;
    const int c0 = lane * 4, c1 = 128 + lane * 4;

    if (t < Kk) sw_[t] = ew[g * Kk + t];

    // ---- embed ----
    {
        float* sEmb = sAg;  // 3200 floats fits in sAg (4160)
        for (int idx = t; idx < Kk * EMBd; idx += 512)
            sEmb[idx] = efea[(size_t)g * Kk * EMBd + idx];
        __syncthreads();
        if (t < Kk) slog[t] = log2f(sw_[t]);
        const int f = t & 63, q = t >> 6;
        if (f < Ff - 1) {
            float a0 = bi[f], a1 = bi[f];
            #pragma unroll 4
            for (int k = 0; k < EMBd; k++) {
                const float wv = Wi[k * (Ff - 1) + f];
                a0 = fmaf(sEmb[(2 * q) * EMBd + k], wv, a0);
                a1 = fmaf(sEmb[(2 * q + 1) * EMBd + k], wv, a1);
            }
            sfeaT[f * 16 + 2 * q]     = a0;
            sfeaT[f * 16 + 2 * q + 1] = a1;
        } else {
            sfeaT[63 * 16 + 2 * q]     = sw_[2 * q];
            sfeaT[63 * 16 + 2 * q + 1] = sw_[2 * q + 1];
        }
        __syncthreads();
    }

    // ---- message passing layers ----
    for (int l = 0; l < Ll; l++) {
        for (int idx = t; idx < Kk * Ff; idx += 512) sdelta[idx] = 0.f;
        __syncthreads();

        for (int h = 0; h < Hh; h++) {
            const int lh = l * Hh + h;

            // projections: gate (threads 0-255) || msg (256-511)
            if (t < 256)
                proj_ab(sfeaT, sAg, sBg, gW1 + (size_t)lh * 2 * Ff * HIDd,
                        gb1 + lh * HIDd, t);
            else
                proj_ab(sfeaT, sAm, sBm, mW1 + (size_t)lh * 2 * Ff * HIDd,
                        mb1 + lh * HIDd, t - 256);
            __syncthreads();

            // ---- warp-local gate + softmax + H; warp wid owns node i=wid --
            {
                const int i = wid;
                // gate A row chunk + gW2 chunk in registers
                u64 a0, a1, a2v, a3v;
                lds128(a0, a1, sm_u32(&sAg[i * S + c0]));
                lds128(a2v, a3v, sm_u32(&sAg[i * S + c1]));
                const float4 wa = *(const float4*)&gW2[lh * HIDd + c0];
                const float4 wb = *(const float4*)&gW2[lh * HIDd + c1];
                const u64 w0 = pack2(wa.x, wa.y), w1 = pack2(wa.z, wa.w);
                const u64 w2v = pack2(wb.x, wb.y), w3v = pack2(wb.z, wb.w);
                const float gb2v = gb2[lh];

                float myg = -1e30f;
                #pragma unroll 1
                for (int j = 0; j < Kk; j++) {
                    u64 b0, b1v, b2v, b3v;
                    lds128(b0, b1v, sm_u32(&sBg[j * S + c0]));
                    lds128(b2v, b3v, sm_u32(&sBg[j * S + c1]));
                    u64 acc = mul2(selu2(add2(a0, b0)), w0);
                    acc = fma2(selu2(add2(a1, b1v)), w1, acc);
                    acc = fma2(selu2(add2(a2v, b2v)), w2v, acc);
                    acc = fma2(selu2(add2(a3v, b3v)), w3v, acc);
                    float s0, s1; unpack2(acc, s0, s1);
                    float p = s0 + s1;
                    p += shxor(p, 16); p += shxor(p, 8);
                    p += shxor(p, 4);  p += shxor(p, 2); p += shxor(p, 1);
                    if (lane == j) myg = p + gb2v;
                }
                // in-warp softmax over lanes 0..15 (lane = j); diag -> 0
                if (lane == i) myg = -1e30f;
                float gmax = myg;
                gmax = fmaxf(gmax, shxor(gmax, 1));
                gmax = fmaxf(gmax, shxor(gmax, 2));
                gmax = fmaxf(gmax, shxor(gmax, 4));
                gmax = fmaxf(gmax, shxor(gmax, 8));
                float aval = 0.f;
                if (lane < Kk)
                    aval = exp2f(m_pow[lh] * slog[lane]) * __expf(myg - gmax);
                float den = aval;
                den += shxor(den, 1); den += shxor(den, 2);
                den += shxor(den, 4); den += shxor(den, 8);
                den += 1e-10f;
                const float my_attn = aval / den;
                if (lane == 0) ssum[i] = (den - 1e-10f) / den;

                // H[i,c] = sum_j attn_j * selu(mA[i,c] + mB[j,c])
                u64 va0, va1, va2, va3;
                lds128(va0, va1, sm_u32(&sAm[i * S + c0]));
                lds128(va2, va3, sm_u32(&sAm[i * S + c1]));
                u64 h0 = pack2(0.f, 0.f), h1 = h0, h2 = h0, h3 = h0;
                #pragma unroll 1
                for (int j = 0; j < Kk; j++) {
                    const float ajf = __shfl_sync(0xffffffffu, my_attn, j);
                    const u64 aj2 = pack2(ajf, ajf);
                    u64 b0, b1v, b2v, b3v;
                    lds128(b0, b1v, sm_u32(&sBm[j * S + c0]));
                    lds128(b2v, b3v, sm_u32(&sBm[j * S + c1]));
                    h0 = fma2(selu2(add2(va0, b0)), aj2, h0);
                    h1 = fma2(selu2(add2(va1, b1v)), aj2, h1);
                    h2 = fma2(selu2(add2(va2, b2v)), aj2, h2);
                    h3 = fma2(selu2(add2(va3, b3v)), aj2, h3);
                }
                // overwrite own gate-A row (only this warp touches row i)
                sts128(sm_u32(&sH[i * S + c0]), h0, h1);
                sts128(sm_u32(&sH[i * S + c1]), h2, h3);
            }
            __syncthreads();

            // delta[i,f] += H[i,:] @ W2[:,f] + ssum[i]*mb2[f]
            {
                const int i = wid, fb = lane * 2;
                const float* W2 = mW2 + (size_t)lh * HIDd * Ff;
                const float* b2 = mb2 + lh * Ff;
                const float si = ssum[i];
                float a0 = si * b2[fb], a1 = si * b2[fb + 1];
                #pragma unroll 4
                for (int tt = 0; tt < HIDd; tt++) {
                    const float hv = sH[i * S + tt];
                    const float2 w = *(const float2*)&W2[tt * Ff + fb];
                    a0 = fmaf(hv, w.x, a0);
                    a1 = fmaf(hv, w.y, a1);
                }
                sdelta[i * Ff + fb]     += a0;
                sdelta[i * Ff + fb + 1] += a1;
            }
            __syncthreads();
        }

        // residual: fea += mean over heads
        for (int idx = t; idx < Kk * Ff; idx += 512) {
            const int i = idx >> 6, f = idx & 63;
            sfeaT[f * 16 + i] += sdelta[idx] * (1.f / Hh);
        }
        __syncthreads();
    }

    // ---- cry pooling ----
    if (t < Ff) sout[t] = 0.f;
    __syncthreads();

    for (int h = 0; h < Hh; h++) {
        if (t < 256)
            proj_pass(sfeaT, sAg, cgW1 + (size_t)h * Ff * HIDd,
                      cgb1[h * HIDd + t], t);
        else
            proj_pass(sfeaT, sAm, cmW1 + (size_t)h * Ff * HIDd,
                      cmb1[h * HIDd + (t - 256)], t - 256);
        __syncthreads();

        // node gate: warp wid owns node n=wid, full 256-dot across lanes
        {
            const int n = wid;
            u64 a0, a1, a2v, a3v;
            lds128(a0, a1, sm_u32(&sAg[n * S + c0]));
            lds128(a2v, a3v, sm_u32(&sAg[n * S + c1]));
            const float4 wa = *(const float4*)&cgW2[h * HIDd + c0];
            const float4 wb = *(const float4*)&cgW2[h * HIDd + c1];
            u64 acc = mul2(selu2(a0), pack2(wa.x, wa.y));
            acc = fma2(selu2(a1), pack2(wa.z, wa.w), acc);
            acc = fma2(selu2(a2v), pack2(wb.x, wb.y), acc);
            acc = fma2(selu2(a3v), pack2(wb.z, wb.w), acc);
            float s0, s1; unpack2(acc, s0, s1);
            float p = s0 + s1;
            p += shxor(p, 16); p += shxor(p, 8);
            p += shxor(p, 4);  p += shxor(p, 2); p += shxor(p, 1);
            if (lane == 0) sgc[n] = p + cgb2[h];
        }
        __syncthreads();

        // softmax over 16 nodes in warp 0
        if (t < 32) {
            float gv = (t < Kk) ? sgc[t] : -1e30f;
            float gmax = gv;
            gmax = fmaxf(gmax, shxor(gmax, 1));
            gmax = fmaxf(gmax, shxor(gmax, 2));
            gmax = fmaxf(gmax, shxor(gmax, 4));
            gmax = fmaxf(gmax, shxor(gmax, 8));
            float aval = 0.f;
            if (t < Kk)
                aval = exp2f(c_pow[h] * slog[t]) * __expf(gv - gmax);
            float den = aval;
            den += shxor(den, 1); den += shxor(den, 2);
            den += shxor(den, 4); den += shxor(den, 8);
            den += 1e-10f;
            if (t < Kk) sac[t] = aval / den;
            if (t == 0) ssum[0] = (den - 1e-10f) / den;
        }
        __syncthreads();

        // Hc[c] = sum_n attn[n]*selu(mA[n,c])
        if (t < HIDd) {
            float hc = 0.f;
            #pragma unroll
            for (int n = 0; n < Kk; n++)
                hc = fmaf(sac[n], selu_f(sAm[n * S + t]), hc);
            sHc[t] = hc;
        }
        __syncthreads();

        // out[f] += Hc @ cmW2[:,f] + ssum*cmb2[f]
        {
            const int f = t & 63, qt = t >> 6;
            const float* W2 = cmW2 + (size_t)h * HIDd * Ff;
            float p = 0.f;
            #pragma unroll 4
            for (int tt = qt * 32; tt < qt * 32 + 32; tt++)
                p = fmaf(sHc[tt], W2[tt * Ff + f], p);
            sred[qt * 64 + f] = p;
        }
        __syncthreads();
        if (t < Ff) {
            float s = ssum[0] * cmb2[h * Ff + t];
            #pragma unroll
            for (int q = 0; q < 8; q++) s += sred[q * 64 + t];
            sout[t] += s;
        }
        __syncthreads();
    }

    if (t < Ff) out[g * Ff + t] = sout[t] * (1.f / Hh);
}

// ---------------------------------------------------------------------------

extern "C" void kernel_launch(void* const* d_in, const int* in_sizes, int n_in,
                              void* d_out, int out_size) {
    const float* elem_weights = (const float*)d_in[0];
    const float* elem_fea_in  = (const float*)d_in[1];
    const float* W_init = (const float*)d_in[2];
    const float* b_init = (const float*)d_in[3];
    const float* mg_W1  = (const float*)d_in[4];
    const float* mg_b1  = (const float*)d_in[5];
    const float* mg_W2  = (const float*)d_in[6];
    const float* mg_b2  = (const float*)d_in[7];
    const float* mm_W1  = (const float*)d_in[8];
    const float* mm_b1  = (const float*)d_in[9];
    const float* mm_W2  = (const float*)d_in[10];
    const float* mm_b2  = (const float*)d_in[11];
    const float* m_pow  = (const float*)d_in[12];
    const float* cg_W1  = (const float*)d_in[13];
    const float* cg_b1  = (const float*)d_in[14];
    const float* cg_W2  = (const float*)d_in[15];
    const float* cg_b2  = (const float*)d_in[16];
    const float* cm_W1  = (const float*)d_in[17];
    const float* cm_b1  = (const float*)d_in[18];
    const float* cm_W2  = (const float*)d_in[19];
    const float* cm_b2  = (const float*)d_in[20];
    const float* c_pow  = (const float*)d_in[21];
    // d_in[22] = batch, d_in[23] = self_idx, d_in[24] = nbr_idx: implicit
    float* out = (float*)d_out;

    const int SMEM = (1024 + 1024 + 4 * 16 * S + 16 * 5 + 64 + 512)
                     * (int)sizeof(float);  // 77376 B
    cudaFuncSetAttribute((const void*)fused_kernel,
                         cudaFuncAttributeMaxDynamicSharedMemorySize, SMEM);

    fused_kernel<<<Gg, 512, SMEM>>>(
        elem_weights, elem_fea_in, W_init, b_init,
        mg_W1, mg_b1, mg_W2, mg_b2, mm_W1, mm_b1, mm_W2, mm_b2, m_pow,
        cg_W1, cg_b1, cg_W2, cg_b2, cm_W1, cm_b1, cm_W2, cm_b2, c_pow,
        out);
}

// round 9
// speedup vs baseline: 7.4442x; 1.0587x over previous
#include <cuda_runtime.h>
#include <math.h>

// Problem constants (fixed by setup_inputs)
#define Gg   256
#define Kk   16
#define Ll   3
#define Hh   3
#define Ff   64
#define EMBd 200
#define HIDd 256
#define DEG  15
#define S    260    // padded smem row stride (floats); row start 16B-aligned

typedef unsigned long long u64;

__device__ __forceinline__ u64 pack2(float lo, float hi) {
    u64 r; asm("mov.b64 %0, {%1, %2};" : "=l"(r) : "f"(lo), "f"(hi)); return r;
}
__device__ __forceinline__ void unpack2(u64 v, float& a, float& b) {
    asm("mov.b64 {%0, %1}, %2;" : "=f"(a), "=f"(b) : "l"(v));
}
__device__ __forceinline__ u64 fma2(u64 a, u64 b, u64 c) {
    u64 d; asm("fma.rn.f32x2 %0, %1, %2, %3;" : "=l"(d) : "l"(a), "l"(b), "l"(c));
    return d;
}
__device__ __forceinline__ u64 mul2(u64 a, u64 b) {
    u64 d; asm("mul.rn.f32x2 %0, %1, %2;" : "=l"(d) : "l"(a), "l"(b)); return d;
}
__device__ __forceinline__ u64 add2(u64 a, u64 b) {
    u64 d; asm("add.rn.f32x2 %0, %1, %2;" : "=l"(d) : "l"(a), "l"(b)); return d;
}
__device__ __forceinline__ void lds128(u64& p01, u64& p23, unsigned addr) {
    asm volatile("ld.shared.v2.b64 {%0, %1}, [%2];"
                 : "=l"(p01), "=l"(p23) : "r"(addr));
}
__device__ __forceinline__ void sts128(unsigned addr, u64 p01, u64 p23) {
    asm volatile("st.shared.v2.b64 [%0], {%1, %2};"
                 :: "r"(addr), "l"(p01), "l"(p23));
}
__device__ __forceinline__ unsigned sm_u32(const void* p) {
    unsigned r;
    asm("{ .reg .u64 t; cvta.to.shared.u64 t, %1; cvt.u32.u64 %0, t; }"
        : "=r"(r) : "l"(p));
    return r;
}

#define SELU_SC 1.0507009873554805f
#define SELU_SA 1.7580993408473766f

__device__ __forceinline__ float selu_f(float x) {
    return x > 0.f ? SELU_SC * x : SELU_SA * (__expf(x) - 1.f);
}

__device__ __forceinline__ u64 selu2(u64 x2) {
    float x0, x1; unpack2(x2, x0, x1);
    const float e0 = __expf(x0), e1 = __expf(x1);
    const u64 n2 = fma2(pack2(e0, e1),
                        pack2(SELU_SA, SELU_SA),
                        pack2(-SELU_SA, -SELU_SA));
    const u64 p2 = mul2(x2, pack2(SELU_SC, SELU_SC));
    float n0, n1, p0, p1;
    unpack2(n2, n0, n1);
    unpack2(p2, p0, p1);
    return pack2(x0 > 0.f ? p0 : n0, x1 > 0.f ? p1 : n1);
}

// One pass of a [16 x 64] @ [64 x 256] projection. u = hidden col (0..255).
__device__ __forceinline__ void proj_pass(const float* __restrict__ sfeaT,
                                          float* __restrict__ Dst,
                                          const float* __restrict__ W1,
                                          float bias, int u) {
    u64 acc[8];
    const u64 bv2 = pack2(bias, bias);
    #pragma unroll
    for (int m = 0; m < 8; m++) acc[m] = bv2;
    const unsigned fa = sm_u32(sfeaT);
    #pragma unroll 4
    for (int k = 0; k < Ff; k++) {
        const float w = W1[k * HIDd + u];
        const u64 w2 = pack2(w, w);
        u64 f0, f1, f2, f3, f4, f5, f6, f7;
        lds128(f0, f1, fa + (k * 16 + 0) * 4);
        lds128(f2, f3, fa + (k * 16 + 4) * 4);
        lds128(f4, f5, fa + (k * 16 + 8) * 4);
        lds128(f6, f7, fa + (k * 16 + 12) * 4);
        acc[0] = fma2(f0, w2, acc[0]);
        acc[1] = fma2(f1, w2, acc[1]);
        acc[2] = fma2(f2, w2, acc[2]);
        acc[3] = fma2(f3, w2, acc[3]);
        acc[4] = fma2(f4, w2, acc[4]);
        acc[5] = fma2(f5, w2, acc[5]);
        acc[6] = fma2(f6, w2, acc[6]);
        acc[7] = fma2(f7, w2, acc[7]);
    }
    #pragma unroll
    for (int m = 0; m < 8; m++) {
        float x, y;
        unpack2(acc[m], x, y);
        Dst[(2 * m) * S + u] = x;
        Dst[(2 * m + 1) * S + u] = y;
    }
}

__device__ __forceinline__ void proj_ab(const float* __restrict__ sfeaT,
                                        float* __restrict__ A,
                                        float* __restrict__ B,
                                        const float* __restrict__ W1,
                                        const float* __restrict__ b1, int u) {
    proj_pass(sfeaT, A, W1, b1[u], u);
    proj_pass(sfeaT, B, W1 + Ff * HIDd, 0.f, u);
}

__device__ __forceinline__ float shxor(float v, int o) {
    return __shfl_xor_sync(0xffffffffu, v, o);
}

#define CSWAP(c, x, y) do { if (c) { float _t = (x); (x) = (y); (y) = _t; } } while (0)

// ---------------------------------------------------------------------------
// One block = one graph. 512 threads. Per head: [parallel gate/msg proj] ->
// barrier -> [warp-per-node: 16 independent gate-dot chains, batched
// 8-value butterfly reduce (lane j = (lane>>2)&7), lane-replicated softmax,
// H accumulation] -> syncwarp -> [W2, delta in registers across heads] ->
// barrier. sfeaT updated once per layer from the register deltas.
// ---------------------------------------------------------------------------
__global__ void __launch_bounds__(512, 2)
fused_kernel(const float* __restrict__ ew, const float* __restrict__ efea,
             const float* __restrict__ Wi, const float* __restrict__ bi,
             const float* __restrict__ gW1, const float* __restrict__ gb1,
             const float* __restrict__ gW2, const float* __restrict__ gb2,
             const float* __restrict__ mW1, const float* __restrict__ mb1,
             const float* __restrict__ mW2, const float* __restrict__ mb2,
             const float* __restrict__ m_pow,
             const float* __restrict__ cgW1, const float* __restrict__ cgb1,
             const float* __restrict__ cgW2, const float* __restrict__ cgb2,
             const float* __restrict__ cmW1, const float* __restrict__ cmb1,
             const float* __restrict__ cmW2, const float* __restrict__ cmb2,
             const float* __restrict__ c_pow,
             float* __restrict__ out) {
    extern __shared__ float sm[];
    float* sfeaT  = sm;                 // [64][16]
    float* sAg    = sm + 1024;          // [16][S] gate A (aliased as sH)
    float* sBg    = sAg + 16 * S;       // [16][S] gate B (aliased as sHc)
    float* sAm    = sBg + 16 * S;       // [16][S] msg A
    float* sBm    = sAm + 16 * S;       // [16][S] msg B
    float* sw_    = sBm + 16 * S;       // [16]
    float* slog   = sw_ + 16;           // [16]  log2(weights)
    float* sgc    = slog + 16;          // [16]  cry gates
    float* sac    = sgc + 16;           // [16]  cry attn
    float* ssum0  = sac + 16;           // [16]  (slot 0 used)
    float* sout   = ssum0 + 16;         // [64]
    float* sred   = sout + 64;          // [8][64]
    float* sH     = sAg;                // alias (row i used by warp i only)
    float* sHc    = sBg;                // alias

    const int g = blockIdx.x;
    const int t = threadIdx.x;
    const int wid = t >> 5, lane = t & 31;
    const int c0 = lane * 4, c1 = 128 + lane * 4;
    const int fb = lane * 2;

    if (t < Kk) sw_[t] = ew[g * Kk + t];

    // ---- embed ----
    {
        float* sEmb = sAg;  // 3200 floats fits in sAg (4160)
        for (int idx = t; idx < Kk * EMBd; idx += 512)
            sEmb[idx] = efea[(size_t)g * Kk * EMBd + idx];
        __syncthreads();
        if (t < Kk) slog[t] = log2f(sw_[t]);
        const int f = t & 63, q = t >> 6;
        if (f < Ff - 1) {
            float a0 = bi[f], a1 = bi[f];
            #pragma unroll 4
            for (int k = 0; k < EMBd; k++) {
                const float wv = Wi[k * (Ff - 1) + f];
                a0 = fmaf(sEmb[(2 * q) * EMBd + k], wv, a0);
                a1 = fmaf(sEmb[(2 * q + 1) * EMBd + k], wv, a1);
            }
            sfeaT[f * 16 + 2 * q]     = a0;
            sfeaT[f * 16 + 2 * q + 1] = a1;
        } else {
            sfeaT[63 * 16 + 2 * q]     = sw_[2 * q];
            sfeaT[63 * 16 + 2 * q + 1] = sw_[2 * q + 1];
        }
        __syncthreads();
    }

    // ---- message passing layers ----
    for (int l = 0; l < Ll; l++) {
        u64 d = pack2(0.f, 0.f);   // delta accumulator: node wid, feats fb,fb+1

        for (int h = 0; h < Hh; h++) {
            const int lh = l * Hh + h;

            // projections: gate (threads 0-255) || msg (256-511)
            if (t < 256)
                proj_ab(sfeaT, sAg, sBg, gW1 + (size_t)lh * 2 * Ff * HIDd,
                        gb1 + lh * HIDd, t);
            else
                proj_ab(sfeaT, sAm, sBm, mW1 + (size_t)lh * 2 * Ff * HIDd,
                        mb1 + lh * HIDd, t - 256);
            __syncthreads();

            // ---- warp-local gate + softmax + H; warp wid owns node i=wid --
            {
                const int i = wid;
                u64 a0, a1, a2v, a3v;
                lds128(a0, a1, sm_u32(&sAg[i * S + c0]));
                lds128(a2v, a3v, sm_u32(&sAg[i * S + c1]));
                const float4 wa = *(const float4*)&gW2[lh * HIDd + c0];
                const float4 wb = *(const float4*)&gW2[lh * HIDd + c1];
                const u64 w0 = pack2(wa.x, wa.y), w1 = pack2(wa.z, wa.w);
                const u64 w2v = pack2(wb.x, wb.y), w3v = pack2(wb.z, wb.w);

                // 16 independent dot chains; batched butterfly reduce (8/batch)
                float gv0, gv1;
                #pragma unroll
                for (int bb = 0; bb < 2; bb++) {
                    float p[8];
                    #pragma unroll
                    for (int m = 0; m < 8; m++) {
                        const int j = bb * 8 + m;
                        u64 b0, b1v, b2v, b3v;
                        lds128(b0, b1v, sm_u32(&sBg[j * S + c0]));
                        lds128(b2v, b3v, sm_u32(&sBg[j * S + c1]));
                        u64 acc = mul2(selu2(add2(a0, b0)), w0);
                        acc = fma2(selu2(add2(a1, b1v)), w1, acc);
                        acc = fma2(selu2(add2(a2v, b2v)), w2v, acc);
                        acc = fma2(selu2(add2(a3v, b3v)), w3v, acc);
                        float s0, s1; unpack2(acc, s0, s1);
                        p[m] = s0 + s1;
                    }
                    const bool s4 = (lane & 16) != 0;
                    const bool s3 = (lane & 8) != 0;
                    const bool s2 = (lane & 4) != 0;
                    CSWAP(s4, p[0], p[4]); CSWAP(s4, p[1], p[5]);
                    CSWAP(s4, p[2], p[6]); CSWAP(s4, p[3], p[7]);
                    p[0] += shxor(p[4], 16); p[1] += shxor(p[5], 16);
                    p[2] += shxor(p[6], 16); p[3] += shxor(p[7], 16);
                    CSWAP(s3, p[0], p[2]); CSWAP(s3, p[1], p[3]);
                    p[0] += shxor(p[2], 8); p[1] += shxor(p[3], 8);
                    CSWAP(s2, p[0], p[1]);
                    p[0] += shxor(p[1], 4);
                    p[0] += shxor(p[0], 2);
                    p[0] += shxor(p[0], 1);
                    if (bb == 0) gv0 = p[0]; else gv1 = p[0];
                }
                // lane holds gates for j = jl (batch0) and jl+8 (batch1)
                const int jl = (lane >> 2) & 7;
                const float gb2v = gb2[lh];
                float g0 = gv0 + gb2v, g1 = gv1 + gb2v;
                if (jl == i)     g0 = -1e30f;   // no self edge
                if (jl + 8 == i) g1 = -1e30f;
                float gmax = fmaxf(g0, g1);
                gmax = fmaxf(gmax, shxor(gmax, 4));
                gmax = fmaxf(gmax, shxor(gmax, 8));
                gmax = fmaxf(gmax, shxor(gmax, 16));
                const float pw = m_pow[lh];
                float av0 = exp2f(pw * slog[jl])     * __expf(g0 - gmax);
                float av1 = exp2f(pw * slog[jl + 8]) * __expf(g1 - gmax);
                float den = av0 + av1;
                den += shxor(den, 4); den += shxor(den, 8); den += shxor(den, 16);
                den += 1e-10f;
                const float at0 = av0 / den, at1 = av1 / den;
                const float ssumv = (den - 1e-10f) / den;

                // H[i,c] = sum_j attn_j * selu(mA[i,c] + mB[j,c])
                u64 va0, va1, va2, va3;
                lds128(va0, va1, sm_u32(&sAm[i * S + c0]));
                lds128(va2, va3, sm_u32(&sAm[i * S + c1]));
                u64 h0 = pack2(0.f, 0.f), h1 = h0, h2 = h0, h3 = h0;
                #pragma unroll 2
                for (int j = 0; j < 8; j++) {
                    const float ajf = __shfl_sync(0xffffffffu, at0, 4 * j);
                    const u64 aj2 = pack2(ajf, ajf);
                    u64 b0, b1v, b2v, b3v;
                    lds128(b0, b1v, sm_u32(&sBm[j * S + c0]));
                    lds128(b2v, b3v, sm_u32(&sBm[j * S + c1]));
                    h0 = fma2(selu2(add2(va0, b0)), aj2, h0);
                    h1 = fma2(selu2(add2(va1, b1v)), aj2, h1);
                    h2 = fma2(selu2(add2(va2, b2v)), aj2, h2);
                    h3 = fma2(selu2(add2(va3, b3v)), aj2, h3);
                }
                #pragma unroll 2
                for (int j = 8; j < 16; j++) {
                    const float ajf = __shfl_sync(0xffffffffu, at1, 4 * (j - 8));
                    const u64 aj2 = pack2(ajf, ajf);
                    u64 b0, b1v, b2v, b3v;
                    lds128(b0, b1v, sm_u32(&sBm[j * S + c0]));
                    lds128(b2v, b3v, sm_u32(&sBm[j * S + c1]));
                    h0 = fma2(selu2(add2(va0, b0)), aj2, h0);
                    h1 = fma2(selu2(add2(va1, b1v)), aj2, h1);
                    h2 = fma2(selu2(add2(va2, b2v)), aj2, h2);
                    h3 = fma2(selu2(add2(va3, b3v)), aj2, h3);
                }
                sts128(sm_u32(&sH[i * S + c0]), h0, h1);
                sts128(sm_u32(&sH[i * S + c1]), h2, h3);
                __syncwarp();

                // delta(+)= H[i,:] @ W2[:,fb..fb+1] + ssumv*mb2[fb..fb+1]
                {
                    const float2 b2p = *(const float2*)&mb2[lh * Ff + fb];
                    d = fma2(pack2(ssumv, ssumv), pack2(b2p.x, b2p.y), d);
                    const float* W2 = mW2 + (size_t)lh * HIDd * Ff + fb;
                    const unsigned ha = sm_u32(&sH[i * S]);
                    #pragma unroll 2
                    for (int tt = 0; tt < HIDd; tt += 4) {
                        u64 hv01, hv23;
                        lds128(hv01, hv23, ha + tt * 4);
                        float q0, q1, q2, q3;
                        unpack2(hv01, q0, q1);
                        unpack2(hv23, q2, q3);
                        d = fma2(pack2(q0, q0), *(const u64*)&W2[(tt + 0) * Ff], d);
                        d = fma2(pack2(q1, q1), *(const u64*)&W2[(tt + 1) * Ff], d);
                        d = fma2(pack2(q2, q2), *(const u64*)&W2[(tt + 2) * Ff], d);
                        d = fma2(pack2(q3, q3), *(const u64*)&W2[(tt + 3) * Ff], d);
                    }
                }
            }
            __syncthreads();
        }

        // residual: fea += mean over heads (from register deltas)
        {
            float d0, d1; unpack2(d, d0, d1);
            sfeaT[fb * 16 + wid]       += d0 * (1.f / Hh);
            sfeaT[(fb + 1) * 16 + wid] += d1 * (1.f / Hh);
        }
        __syncthreads();
    }

    // ---- cry pooling ----
    if (t < Ff) sout[t] = 0.f;
    __syncthreads();

    for (int h = 0; h < Hh; h++) {
        if (t < 256)
            proj_pass(sfeaT, sAg, cgW1 + (size_t)h * Ff * HIDd,
                      cgb1[h * HIDd + t], t);
        else
            proj_pass(sfeaT, sAm, cmW1 + (size_t)h * Ff * HIDd,
                      cmb1[h * HIDd + (t - 256)], t - 256);
        __syncthreads();

        // node gate: warp wid owns node n=wid
        {
            const int n = wid;
            u64 a0, a1, a2v, a3v;
            lds128(a0, a1, sm_u32(&sAg[n * S + c0]));
            lds128(a2v, a3v, sm_u32(&sAg[n * S + c1]));
            const float4 wa = *(const float4*)&cgW2[h * HIDd + c0];
            const float4 wb = *(const float4*)&cgW2[h * HIDd + c1];
            u64 acc = mul2(selu2(a0), pack2(wa.x, wa.y));
            acc = fma2(selu2(a1), pack2(wa.z, wa.w), acc);
            acc = fma2(selu2(a2v), pack2(wb.x, wb.y), acc);
            acc = fma2(selu2(a3v), pack2(wb.z, wb.w), acc);
            float s0, s1; unpack2(acc, s0, s1);
            float p = s0 + s1;
            p += shxor(p, 16); p += shxor(p, 8);
            p += shxor(p, 4);  p += shxor(p, 2); p += shxor(p, 1);
            if (lane == 0) sgc[n] = p + cgb2[h];
        }
        __syncthreads();

        // softmax over 16 nodes in warp 0
        if (t < 32) {
            float gv = (t < Kk) ? sgc[t] : -1e30f;
            float gmax = gv;
            gmax = fmaxf(gmax, shxor(gmax, 1));
            gmax = fmaxf(gmax, shxor(gmax, 2));
            gmax = fmaxf(gmax, shxor(gmax, 4));
            gmax = fmaxf(gmax, shxor(gmax, 8));
            float aval = 0.f;
            if (t < Kk)
                aval = exp2f(c_pow[h] * slog[t]) * __expf(gv - gmax);
            float den = aval;
            den += shxor(den, 1); den += shxor(den, 2);
            den += shxor(den, 4); den += shxor(den, 8);
            den += 1e-10f;
            if (t < Kk) sac[t] = aval / den;
            if (t == 0) ssum0[0] = (den - 1e-10f) / den;
        }
        __syncthreads();

        // Hc[c] = sum_n attn[n]*selu(mA[n,c])
        if (t < HIDd) {
            float hc = 0.f;
            #pragma unroll
            for (int n = 0; n < Kk; n++)
                hc = fmaf(sac[n], selu_f(sAm[n * S + t]), hc);
            sHc[t] = hc;
        }
        __syncthreads();

        // out[f] += Hc @ cmW2[:,f] + ssum*cmb2[f]
        {
            const int f = t & 63, qt = t >> 6;
            const float* W2 = cmW2 + (size_t)h * HIDd * Ff;
            float p = 0.f;
            #pragma unroll 4
            for (int tt = qt * 32; tt < qt * 32 + 32; tt++)
                p = fmaf(sHc[tt], W2[tt * Ff + f], p);
            sred[qt * 64 + f] = p;
        }
        __syncthreads();
        if (t < Ff) {
            float s = ssum0[0] * cmb2[h * Ff + t];
            #pragma unroll
            for (int q = 0; q < 8; q++) s += sred[q * 64 + t];
            sout[t] += s;
        }
        __syncthreads();
    }

    if (t < Ff) out[g * Ff + t] = sout[t] * (1.f / Hh);
}

// ---------------------------------------------------------------------------

extern "C" void kernel_launch(void* const* d_in, const int* in_sizes, int n_in,
                              void* d_out, int out_size) {
    const float* elem_weights = (const float*)d_in[0];
    const float* elem_fea_in  = (const float*)d_in[1];
    const float* W_init = (const float*)d_in[2];
    const float* b_init = (const float*)d_in[3];
    const float* mg_W1  = (const float*)d_in[4];
    const float* mg_b1  = (const float*)d_in[5];
    const float* mg_W2  = (const float*)d_in[6];
    const float* mg_b2  = (const float*)d_in[7];
    const float* mm_W1  = (const float*)d_in[8];
    const float* mm_b1  = (const float*)d_in[9];
    const float* mm_W2  = (const float*)d_in[10];
    const float* mm_b2  = (const float*)d_in[11];
    const float* m_pow  = (const float*)d_in[12];
    const float* cg_W1  = (const float*)d_in[13];
    const float* cg_b1  = (const float*)d_in[14];
    const float* cg_W2  = (const float*)d_in[15];
    const float* cg_b2  = (const float*)d_in[16];
    const float* cm_W1  = (const float*)d_in[17];
    const float* cm_b1  = (const float*)d_in[18];
    const float* cm_W2  = (const float*)d_in[19];
    const float* cm_b2  = (const float*)d_in[20];
    const float* c_pow  = (const float*)d_in[21];
    // d_in[22] = batch, d_in[23] = self_idx, d_in[24] = nbr_idx: implicit
    float* out = (float*)d_out;

    const int SMEM = (1024 + 4 * 16 * S + 16 * 5 + 64 + 512)
                     * (int)sizeof(float);  // 73280 B
    cudaFuncSetAttribute((const void*)fused_kernel,
                         cudaFuncAttributeMaxDynamicSharedMemorySize, SMEM);

    fused_kernel<<<Gg, 512, SMEM>>>(
        elem_weights, elem_fea_in, W_init, b_init,
        mg_W1, mg_b1, mg_W2, mg_b2, mm_W1, mm_b1, mm_W2, mm_b2, m_pow,
        cg_W1, cg_b1, cg_W2, cg_b2, cm_W1, cm_b1, cm_W2, cm_b2, c_pow,
        out);
}

// round 11
// speedup vs baseline: 8.3061x; 1.1158x over previous
#include <cuda_runtime.h>
#include <math.h>

// Problem constants (fixed by setup_inputs)
#define Gg   256
#define Kk   16
#define Ll   3
#define Hh   3
#define Ff   64
#define EMBd 200
#define HIDd 256
#define DEG  15
#define S    260    // padded smem row stride (floats); row start 16B-aligned

typedef unsigned long long u64;

__device__ __forceinline__ u64 pack2(float lo, float hi) {
    u64 r; asm("mov.b64 %0, {%1, %2};" : "=l"(r) : "f"(lo), "f"(hi)); return r;
}
__device__ __forceinline__ void unpack2(u64 v, float& a, float& b) {
    asm("mov.b64 {%0, %1}, %2;" : "=f"(a), "=f"(b) : "l"(v));
}
__device__ __forceinline__ u64 fma2(u64 a, u64 b, u64 c) {
    u64 d; asm("fma.rn.f32x2 %0, %1, %2, %3;" : "=l"(d) : "l"(a), "l"(b), "l"(c));
    return d;
}
__device__ __forceinline__ u64 mul2(u64 a, u64 b) {
    u64 d; asm("mul.rn.f32x2 %0, %1, %2;" : "=l"(d) : "l"(a), "l"(b)); return d;
}
__device__ __forceinline__ u64 add2(u64 a, u64 b) {
    u64 d; asm("add.rn.f32x2 %0, %1, %2;" : "=l"(d) : "l"(a), "l"(b)); return d;
}
__device__ __forceinline__ void lds128(u64& p01, u64& p23, unsigned addr) {
    asm volatile("ld.shared.v2.b64 {%0, %1}, [%2];"
                 : "=l"(p01), "=l"(p23) : "r"(addr));
}
__device__ __forceinline__ void sts128(unsigned addr, u64 p01, u64 p23) {
    asm volatile("st.shared.v2.b64 [%0], {%1, %2};"
                 :: "r"(addr), "l"(p01), "l"(p23));
}
__device__ __forceinline__ unsigned sm_u32(const void* p) {
    unsigned r;
    asm("{ .reg .u64 t; cvta.to.shared.u64 t, %1; cvt.u32.u64 %0, t; }"
        : "=r"(r) : "l"(p));
    return r;
}

#define SELU_SC 1.0507009873554805f
#define SELU_SA 1.7580993408473766f

__device__ __forceinline__ float selu_f(float x) {
    return x > 0.f ? SELU_SC * x : SELU_SA * (__expf(x) - 1.f);
}

__device__ __forceinline__ u64 selu2(u64 x2) {
    float x0, x1; unpack2(x2, x0, x1);
    const float e0 = __expf(x0), e1 = __expf(x1);
    const u64 n2 = fma2(pack2(e0, e1),
                        pack2(SELU_SA, SELU_SA),
                        pack2(-SELU_SA, -SELU_SA));
    const u64 p2 = mul2(x2, pack2(SELU_SC, SELU_SC));
    float n0, n1, p0, p1;
    unpack2(n2, n0, n1);
    unpack2(p2, p0, p1);
    return pack2(x0 > 0.f ? p0 : n0, x1 > 0.f ? p1 : n1);
}

// Fused A+B projection: one sweep over feaT feeds both weight halves.
//   A[n][u] = sum_k feaT[k][n]*W1[k][u] + b1[u]
//   B[n][u] = sum_k feaT[k][n]*W1[64+k][u]
// 16 u64 accumulators; feaT row loaded once per k (broadcast LDS).
__device__ __forceinline__ void proj_fused(const float* __restrict__ sfeaT,
                                           float* __restrict__ A,
                                           float* __restrict__ B,
                                           const float* __restrict__ W1,
                                           float bias, int u) {
    u64 aA[8], aB[8];
    const u64 bv2 = pack2(bias, bias);
    const u64 z2  = pack2(0.f, 0.f);
    #pragma unroll
    for (int m = 0; m < 8; m++) { aA[m] = bv2; aB[m] = z2; }
    const unsigned fa = sm_u32(sfeaT);
    const float* Wa = W1 + u;
    const float* Wb = W1 + Ff * HIDd + u;
    #pragma unroll 4
    for (int k = 0; k < Ff; k++) {
        const float ws = Wa[k * HIDd];
        const float wn = Wb[k * HIDd];
        const u64 ws2 = pack2(ws, ws);
        const u64 wn2 = pack2(wn, wn);
        u64 f0, f1;
        lds128(f0, f1, fa + (k * 16 + 0) * 4);
        aA[0] = fma2(f0, ws2, aA[0]);  aB[0] = fma2(f0, wn2, aB[0]);
        aA[1] = fma2(f1, ws2, aA[1]);  aB[1] = fma2(f1, wn2, aB[1]);
        lds128(f0, f1, fa + (k * 16 + 4) * 4);
        aA[2] = fma2(f0, ws2, aA[2]);  aB[2] = fma2(f0, wn2, aB[2]);
        aA[3] = fma2(f1, ws2, aA[3]);  aB[3] = fma2(f1, wn2, aB[3]);
        lds128(f0, f1, fa + (k * 16 + 8) * 4);
        aA[4] = fma2(f0, ws2, aA[4]);  aB[4] = fma2(f0, wn2, aB[4]);
        aA[5] = fma2(f1, ws2, aA[5]);  aB[5] = fma2(f1, wn2, aB[5]);
        lds128(f0, f1, fa + (k * 16 + 12) * 4);
        aA[6] = fma2(f0, ws2, aA[6]);  aB[6] = fma2(f0, wn2, aB[6]);
        aA[7] = fma2(f1, ws2, aA[7]);  aB[7] = fma2(f1, wn2, aB[7]);
    }
    #pragma unroll
    for (int m = 0; m < 8; m++) {
        float x, y;
        unpack2(aA[m], x, y);
        A[(2 * m) * S + u] = x;
        A[(2 * m + 1) * S + u] = y;
    }
    #pragma unroll
    for (int m = 0; m < 8; m++) {
        float x, y;
        unpack2(aB[m], x, y);
        B[(2 * m) * S + u] = x;
        B[(2 * m + 1) * S + u] = y;
    }
}

// Single projection (cry nets, input dim 64). 8 accumulators.
__device__ __forceinline__ void proj_pass(const float* __restrict__ sfeaT,
                                          float* __restrict__ Dst,
                                          const float* __restrict__ W1,
                                          float bias, int u) {
    u64 acc[8];
    const u64 bv2 = pack2(bias, bias);
    #pragma unroll
    for (int m = 0; m < 8; m++) acc[m] = bv2;
    const unsigned fa = sm_u32(sfeaT);
    #pragma unroll 4
    for (int k = 0; k < Ff; k++) {
        const float w = W1[k * HIDd + u];
        const u64 w2 = pack2(w, w);
        u64 f0, f1, f2, f3, f4, f5, f6, f7;
        lds128(f0, f1, fa + (k * 16 + 0) * 4);
        lds128(f2, f3, fa + (k * 16 + 4) * 4);
        lds128(f4, f5, fa + (k * 16 + 8) * 4);
        lds128(f6, f7, fa + (k * 16 + 12) * 4);
        acc[0] = fma2(f0, w2, acc[0]);
        acc[1] = fma2(f1, w2, acc[1]);
        acc[2] = fma2(f2, w2, acc[2]);
        acc[3] = fma2(f3, w2, acc[3]);
        acc[4] = fma2(f4, w2, acc[4]);
        acc[5] = fma2(f5, w2, acc[5]);
        acc[6] = fma2(f6, w2, acc[6]);
        acc[7] = fma2(f7, w2, acc[7]);
    }
    #pragma unroll
    for (int m = 0; m < 8; m++) {
        float x, y;
        unpack2(acc[m], x, y);
        Dst[(2 * m) * S + u] = x;
        Dst[(2 * m + 1) * S + u] = y;
    }
}

__device__ __forceinline__ float shxor(float v, int o) {
    return __shfl_xor_sync(0xffffffffu, v, o);
}

#define CSWAP(c, x, y) do { if (c) { float _t = (x); (x) = (y); (y) = _t; } } while (0)

// ---------------------------------------------------------------------------
// One block = one graph. 512 threads. Per head: [parallel fused gate/msg
// projections] -> barrier -> [warp-per-node: 16 independent gate-dot chains,
// batched butterfly reduce, lane-replicated softmax, H accumulation] ->
// syncwarp -> [W2, delta in registers across heads] -> barrier.
// ---------------------------------------------------------------------------
__global__ void __launch_bounds__(512, 2)
fused_kernel(const float* __restrict__ ew, const float* __restrict__ efea,
             const float* __restrict__ Wi, const float* __restrict__ bi,
             const float* __restrict__ gW1, const float* __restrict__ gb1,
             const float* __restrict__ gW2, const float* __restrict__ gb2,
             const float* __restrict__ mW1, const float* __restrict__ mb1,
             const float* __restrict__ mW2, const float* __restrict__ mb2,
             const float* __restrict__ m_pow,
             const float* __restrict__ cgW1, const float* __restrict__ cgb1,
             const float* __restrict__ cgW2, const float* __restrict__ cgb2,
             const float* __restrict__ cmW1, const float* __restrict__ cmb1,
             const float* __restrict__ cmW2, const float* __restrict__ cmb2,
             const float* __restrict__ c_pow,
             float* __restrict__ out) {
    extern __shared__ float sm[];
    float* sfeaT  = sm;                 // [64][16]
    float* sAg    = sm + 1024;          // [16][S] gate A (aliased as sH)
    float* sBg    = sAg + 16 * S;       // [16][S] gate B (aliased as sHc)
    float* sAm    = sBg + 16 * S;       // [16][S] msg A
    float* sBm    = sAm + 16 * S;       // [16][S] msg B
    float* sw_    = sBm + 16 * S;       // [16]
    float* slog   = sw_ + 16;           // [16]  log2(weights)
    float* sgc    = slog + 16;          // [16]  cry gates
    float* sac    = sgc + 16;           // [16]  cry attn
    float* ssum0  = sac + 16;           // [16]  (slot 0 used)
    float* sout   = ssum0 + 16;         // [64]
    float* sred   = sout + 64;          // [8][64]
    float* sH     = sAg;                // alias (row i used by warp i only)
    float* sHc    = sBg;                // alias

    const int g = blockIdx.x;
    const int t = threadIdx.x;
    const int wid = t >> 5, lane = t & 31;
    const int c0 = lane * 4, c1 = 128 + lane * 4;
    const int fb = lane * 2;

    if (t < Kk) sw_[t] = ew[g * Kk + t];

    // ---- embed ----
    {
        float* sEmb = sAg;  // 3200 floats fits in sAg (4160)
        for (int idx = t; idx < Kk * EMBd; idx += 512)
            sEmb[idx] = efea[(size_t)g * Kk * EMBd + idx];
        __syncthreads();
        if (t < Kk) slog[t] = log2f(sw_[t]);
        const int f = t & 63, q = t >> 6;
        if (f < Ff - 1) {
            float a0 = bi[f], a1 = bi[f];
            #pragma unroll 4
            for (int k = 0; k < EMBd; k++) {
                const float wv = Wi[k * (Ff - 1) + f];
                a0 = fmaf(sEmb[(2 * q) * EMBd + k], wv, a0);
                a1 = fmaf(sEmb[(2 * q + 1) * EMBd + k], wv, a1);
            }
            sfeaT[f * 16 + 2 * q]     = a0;
            sfeaT[f * 16 + 2 * q + 1] = a1;
        } else {
            sfeaT[63 * 16 + 2 * q]     = sw_[2 * q];
            sfeaT[63 * 16 + 2 * q + 1] = sw_[2 * q + 1];
        }
        __syncthreads();
    }

    // ---- message passing layers ----
    for (int l = 0; l < Ll; l++) {
        u64 d = pack2(0.f, 0.f);   // delta accumulator: node wid, feats fb,fb+1

        for (int h = 0; h < Hh; h++) {
            const int lh = l * Hh + h;

            // fused projections: gate (threads 0-255) || msg (256-511)
            if (t < 256)
                proj_fused(sfeaT, sAg, sBg, gW1 + (size_t)lh * 2 * Ff * HIDd,
                           gb1[lh * HIDd + t], t);
            else
                proj_fused(sfeaT, sAm, sBm, mW1 + (size_t)lh * 2 * Ff * HIDd,
                           mb1[lh * HIDd + (t - 256)], t - 256);
            __syncthreads();

            // ---- warp-local gate + softmax + H; warp wid owns node i=wid --
            {
                const int i = wid;
                u64 a0, a1, a2v, a3v;
                lds128(a0, a1, sm_u32(&sAg[i * S + c0]));
                lds128(a2v, a3v, sm_u32(&sAg[i * S + c1]));
                const float4 wa = *(const float4*)&gW2[lh * HIDd + c0];
                const float4 wb = *(const float4*)&gW2[lh * HIDd + c1];
                const u64 w0 = pack2(wa.x, wa.y), w1 = pack2(wa.z, wa.w);
                const u64 w2v = pack2(wb.x, wb.y), w3v = pack2(wb.z, wb.w);

                // 16 independent dot chains; batched butterfly reduce (8/batch)
                float gv0, gv1;
                #pragma unroll
                for (int bb = 0; bb < 2; bb++) {
                    float p[8];
                    #pragma unroll
                    for (int m = 0; m < 8; m++) {
                        const int j = bb * 8 + m;
                        u64 b0, b1v, b2v, b3v;
                        lds128(b0, b1v, sm_u32(&sBg[j * S + c0]));
                        lds128(b2v, b3v, sm_u32(&sBg[j * S + c1]));
                        u64 acc = mul2(selu2(add2(a0, b0)), w0);
                        acc = fma2(selu2(add2(a1, b1v)), w1, acc);
                        acc = fma2(selu2(add2(a2v, b2v)), w2v, acc);
                        acc = fma2(selu2(add2(a3v, b3v)), w3v, acc);
                        float s0, s1; unpack2(acc, s0, s1);
                        p[m] = s0 + s1;
                    }
                    const bool s4 = (lane & 16) != 0;
                    const bool s3 = (lane & 8) != 0;
                    const bool s2 = (lane & 4) != 0;
                    CSWAP(s4, p[0], p[4]); CSWAP(s4, p[1], p[5]);
                    CSWAP(s4, p[2], p[6]); CSWAP(s4, p[3], p[7]);
                    p[0] += shxor(p[4], 16); p[1] += shxor(p[5], 16);
                    p[2] += shxor(p[6], 16); p[3] += shxor(p[7], 16);
                    CSWAP(s3, p[0], p[2]); CSWAP(s3, p[1], p[3]);
                    p[0] += shxor(p[2], 8); p[1] += shxor(p[3], 8);
                    CSWAP(s2, p[0], p[1]);
                    p[0] += shxor(p[1], 4);
                    p[0] += shxor(p[0], 2);
                    p[0] += shxor(p[0], 1);
                    if (bb == 0) gv0 = p[0]; else gv1 = p[0];
                }
                // lane holds gates for j = jl (batch0) and jl+8 (batch1)
                const int jl = (lane >> 2) & 7;
                const float gb2v = gb2[lh];
                float g0 = gv0 + gb2v, g1 = gv1 + gb2v;
                if (jl == i)     g0 = -1e30f;   // no self edge
                if (jl + 8 == i) g1 = -1e30f;
                float gmax = fmaxf(g0, g1);
                gmax = fmaxf(gmax, shxor(gmax, 4));
                gmax = fmaxf(gmax, shxor(gmax, 8));
                gmax = fmaxf(gmax, shxor(gmax, 16));
                const float pw = m_pow[lh];
                float av0 = exp2f(pw * slog[jl])     * __expf(g0 - gmax);
                float av1 = exp2f(pw * slog[jl + 8]) * __expf(g1 - gmax);
                float den = av0 + av1;
                den += shxor(den, 4); den += shxor(den, 8); den += shxor(den, 16);
                den += 1e-10f;
                const float at0 = av0 / den, at1 = av1 / den;
                const float ssumv = (den - 1e-10f) / den;

                // H[i,c] = sum_j attn_j * selu(mA[i,c] + mB[j,c])
                u64 va0, va1, va2, va3;
                lds128(va0, va1, sm_u32(&sAm[i * S + c0]));
                lds128(va2, va3, sm_u32(&sAm[i * S + c1]));
                u64 h0 = pack2(0.f, 0.f), h1 = h0, h2 = h0, h3 = h0;
                #pragma unroll 2
                for (int j = 0; j < 8; j++) {
                    const float ajf = __shfl_sync(0xffffffffu, at0, 4 * j);
                    const u64 aj2 = pack2(ajf, ajf);
                    u64 b0, b1v, b2v, b3v;
                    lds128(b0, b1v, sm_u32(&sBm[j * S + c0]));
                    lds128(b2v, b3v, sm_u32(&sBm[j * S + c1]));
                    h0 = fma2(selu2(add2(va0, b0)), aj2, h0);
                    h1 = fma2(selu2(add2(va1, b1v)), aj2, h1);
                    h2 = fma2(selu2(add2(va2, b2v)), aj2, h2);
                    h3 = fma2(selu2(add2(va3, b3v)), aj2, h3);
                }
                #pragma unroll 2
                for (int j = 8; j < 16; j++) {
                    const float ajf = __shfl_sync(0xffffffffu, at1, 4 * (j - 8));
                    const u64 aj2 = pack2(ajf, ajf);
                    u64 b0, b1v, b2v, b3v;
                    lds128(b0, b1v, sm_u32(&sBm[j * S + c0]));
                    lds128(b2v, b3v, sm_u32(&sBm[j * S + c1]));
                    h0 = fma2(selu2(add2(va0, b0)), aj2, h0);
                    h1 = fma2(selu2(add2(va1, b1v)), aj2, h1);
                    h2 = fma2(selu2(add2(va2, b2v)), aj2, h2);
                    h3 = fma2(selu2(add2(va3, b3v)), aj2, h3);
                }
                sts128(sm_u32(&sH[i * S + c0]), h0, h1);
                sts128(sm_u32(&sH[i * S + c1]), h2, h3);
                __syncwarp();

                // delta(+)= H[i,:] @ W2[:,fb..fb+1] + ssumv*mb2[fb..fb+1]
                {
                    const float2 b2p = *(const float2*)&mb2[lh * Ff + fb];
                    d = fma2(pack2(ssumv, ssumv), pack2(b2p.x, b2p.y), d);
                    const float* W2 = mW2 + (size_t)lh * HIDd * Ff + fb;
                    const unsigned ha = sm_u32(&sH[i * S]);
                    #pragma unroll 2
                    for (int tt = 0; tt < HIDd; tt += 4) {
                        u64 hv01, hv23;
                        lds128(hv01, hv23, ha + tt * 4);
                        float q0, q1, q2, q3;
                        unpack2(hv01, q0, q1);
                        unpack2(hv23, q2, q3);
                        d = fma2(pack2(q0, q0), *(const u64*)&W2[(tt + 0) * Ff], d);
                        d = fma2(pack2(q1, q1), *(const u64*)&W2[(tt + 1) * Ff], d);
                        d = fma2(pack2(q2, q2), *(const u64*)&W2[(tt + 2) * Ff], d);
                        d = fma2(pack2(q3, q3), *(const u64*)&W2[(tt + 3) * Ff], d);
                    }
                }
            }
            __syncthreads();
        }

        // residual: fea += mean over heads (from register deltas)
        {
            float d0, d1; unpack2(d, d0, d1);
            sfeaT[fb * 16 + wid]       += d0 * (1.f / Hh);
            sfeaT[(fb + 1) * 16 + wid] += d1 * (1.f / Hh);
        }
        __syncthreads();
    }

    // ---- cry pooling ----
    if (t < Ff) sout[t] = 0.f;
    __syncthreads();

    for (int h = 0; h < Hh; h++) {
        if (t < 256)
            proj_pass(sfeaT, sAg, cgW1 + (size_t)h * Ff * HIDd,
                      cgb1[h * HIDd + t], t);
        else
            proj_pass(sfeaT, sAm, cmW1 + (size_t)h * Ff * HIDd,
                      cmb1[h * HIDd + (t - 256)], t - 256);
        __syncthreads();

        // node gate: warp wid owns node n=wid
        {
            const int n = wid;
            u64 a0, a1, a2v, a3v;
            lds128(a0, a1, sm_u32(&sAg[n * S + c0]));
            lds128(a2v, a3v, sm_u32(&sAg[n * S + c1]));
            const float4 wa = *(const float4*)&cgW2[h * HIDd + c0];
            const float4 wb = *(const float4*)&cgW2[h * HIDd + c1];
            u64 acc = mul2(selu2(a0), pack2(wa.x, wa.y));
            acc = fma2(selu2(a1), pack2(wa.z, wa.w), acc);
            acc = fma2(selu2(a2v), pack2(wb.x, wb.y), acc);
            acc = fma2(selu2(a3v), pack2(wb.z, wb.w), acc);
            float s0, s1; unpack2(acc, s0, s1);
            float p = s0 + s1;
            p += shxor(p, 16); p += shxor(p, 8);
            p += shxor(p, 4);  p += shxor(p, 2); p += shxor(p, 1);
            if (lane == 0) sgc[n] = p + cgb2[h];
        }
        __syncthreads();

        // softmax over 16 nodes in warp 0
        if (t < 32) {
            float gv = (t < Kk) ? sgc[t] : -1e30f;
            float gmax = gv;
            gmax = fmaxf(gmax, shxor(gmax, 1));
            gmax = fmaxf(gmax, shxor(gmax, 2));
            gmax = fmaxf(gmax, shxor(gmax, 4));
            gmax = fmaxf(gmax, shxor(gmax, 8));
            float aval = 0.f;
            if (t < Kk)
                aval = exp2f(c_pow[h] * slog[t]) * __expf(gv - gmax);
            float den = aval;
            den += shxor(den, 1); den += shxor(den, 2);
            den += shxor(den, 4); den += shxor(den, 8);
            den += 1e-10f;
            if (t < Kk) sac[t] = aval / den;
            if (t == 0) ssum0[0] = (den - 1e-10f) / den;
        }
        __syncthreads();

        // Hc[c] = sum_n attn[n]*selu(mA[n,c])
        if (t < HIDd) {
            float hc = 0.f;
            #pragma unroll
            for (int n = 0; n < Kk; n++)
                hc = fmaf(sac[n], selu_f(sAm[n * S + t]), hc);
            sHc[t] = hc;
        }
        __syncthreads();

        // out[f] += Hc @ cmW2[:,f] + ssum*cmb2[f]
        {
            const int f = t & 63, qt = t >> 6;
            const float* W2 = cmW2 + (size_t)h * HIDd * Ff;
            float p = 0.f;
            #pragma unroll 4
            for (int tt = qt * 32; tt < qt * 32 + 32; tt++)
                p = fmaf(sHc[tt], W2[tt * Ff + f], p);
            sred[qt * 64 + f] = p;
        }
        __syncthreads();
        if (t < Ff) {
            float s = ssum0[0] * cmb2[h * Ff + t];
            #pragma unroll
            for (int q = 0; q < 8; q++) s += sred[q * 64 + t];
            sout[t] += s;
        }
        __syncthreads();
    }

    if (t < Ff) out[g * Ff + t] = sout[t] * (1.f / Hh);
}

// ---------------------------------------------------------------------------

extern "C" void kernel_launch(void* const* d_in, const int* in_sizes, int n_in,
                              void* d_out, int out_size) {
    const float* elem_weights = (const float*)d_in[0];
    const float* elem_fea_in  = (const float*)d_in[1];
    const float* W_init = (const float*)d_in[2];
    const float* b_init = (const float*)d_in[3];
    const float* mg_W1  = (const float*)d_in[4];
    const float* mg_b1  = (const float*)d_in[5];
    const float* mg_W2  = (const float*)d_in[6];
    const float* mg_b2  = (const float*)d_in[7];
    const float* mm_W1  = (const float*)d_in[8];
    const float* mm_b1  = (const float*)d_in[9];
    const float* mm_W2  = (const float*)d_in[10];
    const float* mm_b2  = (const float*)d_in[11];
    const float* m_pow  = (const float*)d_in[12];
    const float* cg_W1  = (const float*)d_in[13];
    const float* cg_b1  = (const float*)d_in[14];
    const float* cg_W2  = (const float*)d_in[15];
    const float* cg_b2  = (const float*)d_in[16];
    const float* cm_W1  = (const float*)d_in[17];
    const float* cm_b1  = (const float*)d_in[18];
    const float* cm_W2  = (const float*)d_in[19];
    const float* cm_b2  = (const float*)d_in[20];
    const float* c_pow  = (const float*)d_in[21];
    // d_in[22] = batch, d_in[23] = self_idx, d_in[24] = nbr_idx: implicit
    float* out = (float*)d_out;

    const int SMEM = (1024 + 4 * 16 * S + 16 * 5 + 64 + 512)
                     * (int)sizeof(float);  // 73280 B
    cudaFuncSetAttribute((const void*)fused_kernel,
                         cudaFuncAttributeMaxDynamicSharedMemorySize, SMEM);

    fused_kernel<<<Gg, 512, SMEM>>>(
        elem_weights, elem_fea_in, W_init, b_init,
        mg_W1, mg_b1, mg_W2, mg_b2, mm_W1, mm_b1, mm_W2, mm_b2, m_pow,
        cg_W1, cg_b1, cg_W2, cg_b2, cm_W1, cm_b1, cm_W2, cm_b2, c_pow,
        out);
}

// round 16
// speedup vs baseline: 8.9601x; 1.0787x over previous
#include <cuda_runtime.h>
#include <math.h>

// Problem constants (fixed by setup_inputs)
#define Gg   256
#define Kk   16
#define Ll   3
#define Hh   3
#define Ff   64
#define EMBd 200
#define HIDd 256
#define DEG  15
#define S    260    // padded smem row stride (floats); row start 16B-aligned

typedef unsigned long long u64;

__device__ __forceinline__ u64 pack2(float lo, float hi) {
    u64 r; asm("mov.b64 %0, {%1, %2};" : "=l"(r) : "f"(lo), "f"(hi)); return r;
}
__device__ __forceinline__ void unpack2(u64 v, float& a, float& b) {
    asm("mov.b64 {%0, %1}, %2;" : "=f"(a), "=f"(b) : "l"(v));
}
__device__ __forceinline__ u64 fma2(u64 a, u64 b, u64 c) {
    u64 d; asm("fma.rn.f32x2 %0, %1, %2, %3;" : "=l"(d) : "l"(a), "l"(b), "l"(c));
    return d;
}
__device__ __forceinline__ u64 mul2(u64 a, u64 b) {
    u64 d; asm("mul.rn.f32x2 %0, %1, %2;" : "=l"(d) : "l"(a), "l"(b)); return d;
}
__device__ __forceinline__ u64 add2(u64 a, u64 b) {
    u64 d; asm("add.rn.f32x2 %0, %1, %2;" : "=l"(d) : "l"(a), "l"(b)); return d;
}
__device__ __forceinline__ void lds128(u64& p01, u64& p23, unsigned addr) {
    asm volatile("ld.shared.v2.b64 {%0, %1}, [%2];"
                 : "=l"(p01), "=l"(p23) : "r"(addr));
}
__device__ __forceinline__ void sts128(unsigned addr, u64 p01, u64 p23) {
    asm volatile("st.shared.v2.b64 [%0], {%1, %2};"
                 :: "r"(addr), "l"(p01), "l"(p23));
}
__device__ __forceinline__ unsigned sm_u32(const void* p) {
    unsigned r;
    asm("{ .reg .u64 t; cvta.to.shared.u64 t, %1; cvt.u32.u64 %0, t; }"
        : "=r"(r) : "l"(p));
    return r;
}

#define SELU_SC 1.0507009873554805f
#define SELU_SA 1.7580993408473766f

__device__ __forceinline__ float selu_f(float x) {
    return x > 0.f ? SELU_SC * x : SELU_SA * (__expf(x) - 1.f);
}

__device__ __forceinline__ u64 selu2(u64 x2) {
    float x0, x1; unpack2(x2, x0, x1);
    const float e0 = __expf(x0), e1 = __expf(x1);
    const u64 n2 = fma2(pack2(e0, e1),
                        pack2(SELU_SA, SELU_SA),
                        pack2(-SELU_SA, -SELU_SA));
    const u64 p2 = mul2(x2, pack2(SELU_SC, SELU_SC));
    float n0, n1, p0, p1;
    unpack2(n2, n0, n1);
    unpack2(p2, p0, p1);
    return pack2(x0 > 0.f ? p0 : n0, x1 > 0.f ? p1 : n1);
}

// Fused A+B projection: one sweep over feaT feeds both weight halves.
__device__ __forceinline__ void proj_fused(const float* __restrict__ sfeaT,
                                           float* __restrict__ A,
                                           float* __restrict__ B,
                                           const float* __restrict__ W1,
                                           float bias, int u) {
    u64 aA[8], aB[8];
    const u64 bv2 = pack2(bias, bias);
    const u64 z2  = pack2(0.f, 0.f);
    #pragma unroll
    for (int m = 0; m < 8; m++) { aA[m] = bv2; aB[m] = z2; }
    const unsigned fa = sm_u32(sfeaT);
    const float* Wa = W1 + u;
    const float* Wb = W1 + Ff * HIDd + u;
    #pragma unroll 4
    for (int k = 0; k < Ff; k++) {
        const float ws = Wa[k * HIDd];
        const float wn = Wb[k * HIDd];
        const u64 ws2 = pack2(ws, ws);
        const u64 wn2 = pack2(wn, wn);
        u64 f0, f1;
        lds128(f0, f1, fa + (k * 16 + 0) * 4);
        aA[0] = fma2(f0, ws2, aA[0]);  aB[0] = fma2(f0, wn2, aB[0]);
        aA[1] = fma2(f1, ws2, aA[1]);  aB[1] = fma2(f1, wn2, aB[1]);
        lds128(f0, f1, fa + (k * 16 + 4) * 4);
        aA[2] = fma2(f0, ws2, aA[2]);  aB[2] = fma2(f0, wn2, aB[2]);
        aA[3] = fma2(f1, ws2, aA[3]);  aB[3] = fma2(f1, wn2, aB[3]);
        lds128(f0, f1, fa + (k * 16 + 8) * 4);
        aA[4] = fma2(f0, ws2, aA[4]);  aB[4] = fma2(f0, wn2, aB[4]);
        aA[5] = fma2(f1, ws2, aA[5]);  aB[5] = fma2(f1, wn2, aB[5]);
        lds128(f0, f1, fa + (k * 16 + 12) * 4);
        aA[6] = fma2(f0, ws2, aA[6]);  aB[6] = fma2(f0, wn2, aB[6]);
        aA[7] = fma2(f1, ws2, aA[7]);  aB[7] = fma2(f1, wn2, aB[7]);
    }
    #pragma unroll
    for (int m = 0; m < 8; m++) {
        float x, y;
        unpack2(aA[m], x, y);
        A[(2 * m) * S + u] = x;
        A[(2 * m + 1) * S + u] = y;
    }
    #pragma unroll
    for (int m = 0; m < 8; m++) {
        float x, y;
        unpack2(aB[m], x, y);
        B[(2 * m) * S + u] = x;
        B[(2 * m + 1) * S + u] = y;
    }
}

// Single projection (cry nets, input dim 64). 8 accumulators.
__device__ __forceinline__ void proj_pass(const float* __restrict__ sfeaT,
                                          float* __restrict__ Dst,
                                          const float* __restrict__ W1,
                                          float bias, int u) {
    u64 acc[8];
    const u64 bv2 = pack2(bias, bias);
    #pragma unroll
    for (int m = 0; m < 8; m++) acc[m] = bv2;
    const unsigned fa = sm_u32(sfeaT);
    #pragma unroll 4
    for (int k = 0; k < Ff; k++) {
        const float w = W1[k * HIDd + u];
        const u64 w2 = pack2(w, w);
        u64 f0, f1, f2, f3, f4, f5, f6, f7;
        lds128(f0, f1, fa + (k * 16 + 0) * 4);
        lds128(f2, f3, fa + (k * 16 + 4) * 4);
        lds128(f4, f5, fa + (k * 16 + 8) * 4);
        lds128(f6, f7, fa + (k * 16 + 12) * 4);
        acc[0] = fma2(f0, w2, acc[0]);
        acc[1] = fma2(f1, w2, acc[1]);
        acc[2] = fma2(f2, w2, acc[2]);
        acc[3] = fma2(f3, w2, acc[3]);
        acc[4] = fma2(f4, w2, acc[4]);
        acc[5] = fma2(f5, w2, acc[5]);
        acc[6] = fma2(f6, w2, acc[6]);
        acc[7] = fma2(f7, w2, acc[7]);
    }
    #pragma unroll
    for (int m = 0; m < 8; m++) {
        float x, y;
        unpack2(acc[m], x, y);
        Dst[(2 * m) * S + u] = x;
        Dst[(2 * m + 1) * S + u] = y;
    }
}

__device__ __forceinline__ float shxor(float v, int o) {
    return __shfl_xor_sync(0xffffffffu, v, o);
}

#define CSWAP(c, x, y) do { if (c) { float _t = (x); (x) = (y); (y) = _t; } } while (0)

// ---------------------------------------------------------------------------
// One block = one graph. 512 threads. Per head: [fused gate/msg projections]
// -> barrier -> [warp-per-node gate+softmax+H] -> barrier -> [retiled W2:
// warp = 2 nodes x 32 features, deltas register-resident across heads] ->
// barrier. W2 reuse 4x (16KB instead of 64KB of W2 per warp per head).
// ---------------------------------------------------------------------------
__global__ void __launch_bounds__(512, 2)
fused_kernel(const float* __restrict__ ew, const float* __restrict__ efea,
             const float* __restrict__ Wi, const float* __restrict__ bi,
             const float* __restrict__ gW1, const float* __restrict__ gb1,
             const float* __restrict__ gW2, const float* __restrict__ gb2,
             const float* __restrict__ mW1, const float* __restrict__ mb1,
             const float* __restrict__ mW2, const float* __restrict__ mb2,
             const float* __restrict__ m_pow,
             const float* __restrict__ cgW1, const float* __restrict__ cgb1,
             const float* __restrict__ cgW2, const float* __restrict__ cgb2,
             const float* __restrict__ cmW1, const float* __restrict__ cmb1,
             const float* __restrict__ cmW2, const float* __restrict__ cmb2,
             const float* __restrict__ c_pow,
             float* __restrict__ out) {
    extern __shared__ float sm[];
    float* sfeaT  = sm;                 // [64][16]
    float* sAg    = sm + 1024;          // [16][S] gate A (aliased as sH)
    float* sBg    = sAg + 16 * S;       // [16][S] gate B (aliased as sHc)
    float* sAm    = sBg + 16 * S;       // [16][S] msg A
    float* sBm    = sAm + 16 * S;       // [16][S] msg B
    float* sw_    = sBm + 16 * S;       // [16]
    float* slog   = sw_ + 16;           // [16]  log2(weights)
    float* sgc    = slog + 16;          // [16]  cry gates
    float* sac    = sgc + 16;           // [16]  cry attn
    float* ssum0  = sac + 16;           // [16]  per-node attn sums
    float* sout   = ssum0 + 16;         // [64]
    float* sred   = sout + 64;          // [8][64]
    float* sH     = sAg;                // alias (row i written by warp i)
    float* sHc    = sBg;                // alias

    const int g = blockIdx.x;
    const int t = threadIdx.x;
    const int wid = t >> 5, lane = t & 31;
    const int c0 = lane * 4, c1 = 128 + lane * 4;

    // W2-phase mapping: warp owns nodes {n2,n2+1}, features fW..fW+1 (packed)
    const int n2 = (wid & 7) * 2;
    const int fW = (wid >> 3) * 32 + (lane & 15) * 2;
    const int th = lane >> 4;           // tt half

    if (t < Kk) sw_[t] = ew[g * Kk + t];

    // ---- embed ----
    {
        float* sEmb = sAg;  // 3200 floats fits in sAg (4160)
        for (int idx = t; idx < Kk * EMBd; idx += 512)
            sEmb[idx] = efea[(size_t)g * Kk * EMBd + idx];
        __syncthreads();
        if (t < Kk) slog[t] = log2f(sw_[t]);
        const int f = t & 63, q = t >> 6;
        if (f < Ff - 1) {
            float a0 = bi[f], a1 = bi[f];
            #pragma unroll 4
            for (int k = 0; k < EMBd; k++) {
                const float wv = Wi[k * (Ff - 1) + f];
                a0 = fmaf(sEmb[(2 * q) * EMBd + k], wv, a0);
                a1 = fmaf(sEmb[(2 * q + 1) * EMBd + k], wv, a1);
            }
            sfeaT[f * 16 + 2 * q]     = a0;
            sfeaT[f * 16 + 2 * q + 1] = a1;
        } else {
            sfeaT[63 * 16 + 2 * q]     = sw_[2 * q];
            sfeaT[63 * 16 + 2 * q + 1] = sw_[2 * q + 1];
        }
        __syncthreads();
    }

    // ---- message passing layers ----
    for (int l = 0; l < Ll; l++) {
        u64 dn0 = pack2(0.f, 0.f);  // delta acc: node n2,   feats fW,fW+1
        u64 dn1 = pack2(0.f, 0.f);  // delta acc: node n2+1, feats fW,fW+1

        for (int h = 0; h < Hh; h++) {
            const int lh = l * Hh + h;

            // fused projections: gate (threads 0-255) || msg (256-511)
            if (t < 256)
                proj_fused(sfeaT, sAg, sBg, gW1 + (size_t)lh * 2 * Ff * HIDd,
                           gb1[lh * HIDd + t], t);
            else
                proj_fused(sfeaT, sAm, sBm, mW1 + (size_t)lh * 2 * Ff * HIDd,
                           mb1[lh * HIDd + (t - 256)], t - 256);
            __syncthreads();

            // ---- warp-local gate + softmax + H; warp wid owns node i=wid --
            {
                const int i = wid;
                u64 a0, a1, a2v, a3v;
                lds128(a0, a1, sm_u32(&sAg[i * S + c0]));
                lds128(a2v, a3v, sm_u32(&sAg[i * S + c1]));
                const float4 wa = *(const float4*)&gW2[lh * HIDd + c0];
                const float4 wb = *(const float4*)&gW2[lh * HIDd + c1];
                const u64 w0 = pack2(wa.x, wa.y), w1 = pack2(wa.z, wa.w);
                const u64 w2v = pack2(wb.x, wb.y), w3v = pack2(wb.z, wb.w);

                // 16 independent dot chains; batched butterfly reduce
                float gv0, gv1;
                #pragma unroll
                for (int bb = 0; bb < 2; bb++) {
                    float p[8];
                    #pragma unroll
                    for (int m = 0; m < 8; m++) {
                        const int j = bb * 8 + m;
                        u64 b0, b1v, b2v, b3v;
                        lds128(b0, b1v, sm_u32(&sBg[j * S + c0]));
                        lds128(b2v, b3v, sm_u32(&sBg[j * S + c1]));
                        u64 acc = mul2(selu2(add2(a0, b0)), w0);
                        acc = fma2(selu2(add2(a1, b1v)), w1, acc);
                        acc = fma2(selu2(add2(a2v, b2v)), w2v, acc);
                        acc = fma2(selu2(add2(a3v, b3v)), w3v, acc);
                        float s0, s1; unpack2(acc, s0, s1);
                        p[m] = s0 + s1;
                    }
                    const bool s4 = (lane & 16) != 0;
                    const bool s3 = (lane & 8) != 0;
                    const bool s2 = (lane & 4) != 0;
                    CSWAP(s4, p[0], p[4]); CSWAP(s4, p[1], p[5]);
                    CSWAP(s4, p[2], p[6]); CSWAP(s4, p[3], p[7]);
                    p[0] += shxor(p[4], 16); p[1] += shxor(p[5], 16);
                    p[2] += shxor(p[6], 16); p[3] += shxor(p[7], 16);
                    CSWAP(s3, p[0], p[2]); CSWAP(s3, p[1], p[3]);
                    p[0] += shxor(p[2], 8); p[1] += shxor(p[3], 8);
                    CSWAP(s2, p[0], p[1]);
                    p[0] += shxor(p[1], 4);
                    p[0] += shxor(p[0], 2);
                    p[0] += shxor(p[0], 1);
                    if (bb == 0) gv0 = p[0]; else gv1 = p[0];
                }
                const int jl = (lane >> 2) & 7;
                const float gb2v = gb2[lh];
                float g0 = gv0 + gb2v, g1 = gv1 + gb2v;
                if (jl == i)     g0 = -1e30f;   // no self edge
                if (jl + 8 == i) g1 = -1e30f;
                float gmax = fmaxf(g0, g1);
                gmax = fmaxf(gmax, shxor(gmax, 4));
                gmax = fmaxf(gmax, shxor(gmax, 8));
                gmax = fmaxf(gmax, shxor(gmax, 16));
                const float pw = m_pow[lh];
                float av0 = exp2f(pw * slog[jl])     * __expf(g0 - gmax);
                float av1 = exp2f(pw * slog[jl + 8]) * __expf(g1 - gmax);
                float den = av0 + av1;
                den += shxor(den, 4); den += shxor(den, 8); den += shxor(den, 16);
                den += 1e-10f;
                const float at0 = av0 / den, at1 = av1 / den;
                if (lane == 0) ssum0[i] = (den - 1e-10f) / den;

                // H[i,c] = sum_j attn_j * selu(mA[i,c] + mB[j,c])
                u64 va0, va1, va2, va3;
                lds128(va0, va1, sm_u32(&sAm[i * S + c0]));
                lds128(va2, va3, sm_u32(&sAm[i * S + c1]));
                u64 h0 = pack2(0.f, 0.f), h1 = h0, h2 = h0, h3 = h0;
                #pragma unroll 2
                for (int j = 0; j < 8; j++) {
                    const float ajf = __shfl_sync(0xffffffffu, at0, 4 * j);
                    const u64 aj2 = pack2(ajf, ajf);
                    u64 b0, b1v, b2v, b3v;
                    lds128(b0, b1v, sm_u32(&sBm[j * S + c0]));
                    lds128(b2v, b3v, sm_u32(&sBm[j * S + c1]));
                    h0 = fma2(selu2(add2(va0, b0)), aj2, h0);
                    h1 = fma2(selu2(add2(va1, b1v)), aj2, h1);
                    h2 = fma2(selu2(add2(va2, b2v)), aj2, h2);
                    h3 = fma2(selu2(add2(va3, b3v)), aj2, h3);
                }
                #pragma unroll 2
                for (int j = 8; j < 16; j++) {
                    const float ajf = __shfl_sync(0xffffffffu, at1, 4 * (j - 8));
                    const u64 aj2 = pack2(ajf, ajf);
                    u64 b0, b1v, b2v, b3v;
                    lds128(b0, b1v, sm_u32(&sBm[j * S + c0]));
                    lds128(b2v, b3v, sm_u32(&sBm[j * S + c1]));
                    h0 = fma2(selu2(add2(va0, b0)), aj2, h0);
                    h1 = fma2(selu2(add2(va1, b1v)), aj2, h1);
                    h2 = fma2(selu2(add2(va2, b2v)), aj2, h2);
                    h3 = fma2(selu2(add2(va3, b3v)), aj2, h3);
                }
                sts128(sm_u32(&sH[i * S + c0]), h0, h1);
                sts128(sm_u32(&sH[i * S + c1]), h2, h3);
            }
            __syncthreads();   // all sH rows + ssum0 visible block-wide

            // ---- retiled W2: warp = 2 nodes x 32 f; lane = 2 f, tt-half ----
            {
                const float* W2 = mW2 + (size_t)lh * HIDd * Ff + fW;
                if (th == 0) {   // bias once (other half has no bias term)
                    const float2 b2p = *(const float2*)&mb2[lh * Ff + fW];
                    const float s0 = ssum0[n2], s1 = ssum0[n2 + 1];
                    dn0 = fma2(pack2(s0, s0), pack2(b2p.x, b2p.y), dn0);
                    dn1 = fma2(pack2(s1, s1), pack2(b2p.x, b2p.y), dn1);
                }
                const unsigned h0a = sm_u32(&sH[n2 * S]) + th * 512;
                const unsigned h1a = sm_u32(&sH[(n2 + 1) * S]) + th * 512;
                const float* W2t = W2 + th * 128 * Ff;
                #pragma unroll 2
                for (int tt = 0; tt < 128; tt += 4) {
                    u64 p01, p23, q01, q23;
                    lds128(p01, p23, h0a + tt * 4);
                    lds128(q01, q23, h1a + tt * 4);
                    const u64 wv0 = *(const u64*)&W2t[(tt + 0) * Ff];
                    const u64 wv1 = *(const u64*)&W2t[(tt + 1) * Ff];
                    const u64 wv2 = *(const u64*)&W2t[(tt + 2) * Ff];
                    const u64 wv3 = *(const u64*)&W2t[(tt + 3) * Ff];
                    float x0, x1, x2, x3, y0, y1, y2, y3;
                    unpack2(p01, x0, x1); unpack2(p23, x2, x3);
                    unpack2(q01, y0, y1); unpack2(q23, y2, y3);
                    dn0 = fma2(pack2(x0, x0), wv0, dn0);
                    dn0 = fma2(pack2(x1, x1), wv1, dn0);
                    dn0 = fma2(pack2(x2, x2), wv2, dn0);
                    dn0 = fma2(pack2(x3, x3), wv3, dn0);
                    dn1 = fma2(pack2(y0, y0), wv0, dn1);
                    dn1 = fma2(pack2(y1, y1), wv1, dn1);
                    dn1 = fma2(pack2(y2, y2), wv2, dn1);
                    dn1 = fma2(pack2(y3, y3), wv3, dn1);
                }
            }
            __syncthreads();   // protect sH (=sAg) before next head's proj
        }

        // residual: combine tt halves, fea += mean over heads
        {
            dn0 = add2(dn0, __shfl_xor_sync(0xffffffffu, dn0, 16));
            dn1 = add2(dn1, __shfl_xor_sync(0xffffffffu, dn1, 16));
            if (th == 0) {
                float d0, d1;
                unpack2(dn0, d0, d1);
                sfeaT[fW * 16 + n2]       += d0 * (1.f / Hh);
                sfeaT[(fW + 1) * 16 + n2] += d1 * (1.f / Hh);
                unpack2(dn1, d0, d1);
                sfeaT[fW * 16 + n2 + 1]       += d0 * (1.f / Hh);
                sfeaT[(fW + 1) * 16 + n2 + 1] += d1 * (1.f / Hh);
            }
        }
        __syncthreads();
    }

    // ---- cry pooling ----
    if (t < Ff) sout[t] = 0.f;
    __syncthreads();

    for (int h = 0; h < Hh; h++) {
        if (t < 256)
            proj_pass(sfeaT, sAg, cgW1 + (size_t)h * Ff * HIDd,
                      cgb1[h * HIDd + t], t);
        else
            proj_pass(sfeaT, sAm, cmW1 + (size_t)h * Ff * HIDd,
                      cmb1[h * HIDd + (t - 256)], t - 256);
        __syncthreads();

        // node gate: warp wid owns node n=wid
        {
            const int n = wid;
            u64 a0, a1, a2v, a3v;
            lds128(a0, a1, sm_u32(&sAg[n * S + c0]));
            lds128(a2v, a3v, sm_u32(&sAg[n * S + c1]));
            const float4 wa = *(const float4*)&cgW2[h * HIDd + c0];
            const float4 wb = *(const float4*)&cgW2[h * HIDd + c1];
            u64 acc = mul2(selu2(a0), pack2(wa.x, wa.y));
            acc = fma2(selu2(a1), pack2(wa.z, wa.w), acc);
            acc = fma2(selu2(a2v), pack2(wb.x, wb.y), acc);
            acc = fma2(selu2(a3v), pack2(wb.z, wb.w), acc);
            float s0, s1; unpack2(acc, s0, s1);
            float p = s0 + s1;
            p += shxor(p, 16); p += shxor(p, 8);
            p += shxor(p, 4);  p += shxor(p, 2); p += shxor(p, 1);
            if (lane == 0) sgc[n] = p + cgb2[h];
        }
        __syncthreads();

        // softmax over 16 nodes in warp 0
        if (t < 32) {
            float gv = (t < Kk) ? sgc[t] : -1e30f;
            float gmax = gv;
            gmax = fmaxf(gmax, shxor(gmax, 1));
            gmax = fmaxf(gmax, shxor(gmax, 2));
            gmax = fmaxf(gmax, shxor(gmax, 4));
            gmax = fmaxf(gmax, shxor(gmax, 8));
            float aval = 0.f;
            if (t < Kk)
                aval = exp2f(c_pow[h] * slog[t]) * __expf(gv - gmax);
            float den = aval;
            den += shxor(den, 1); den += shxor(den, 2);
            den += shxor(den, 4); den += shxor(den, 8);
            den += 1e-10f;
            if (t < Kk) sac[t] = aval / den;
            if (t == 0) ssum0[0] = (den - 1e-10f) / den;
        }
        __syncthreads();

        // Hc[c] = sum_n attn[n]*selu(mA[n,c])
        if (t < HIDd) {
            float hc = 0.f;
            #pragma unroll
            for (int n = 0; n < Kk; n++)
                hc = fmaf(sac[n], selu_f(sAm[n * S + t]), hc);
            sHc[t] = hc;
        }
        __syncthreads();

        // out[f] += Hc @ cmW2[:,f] + ssum*cmb2[f]
        {
            const int f = t & 63, qt = t >> 6;
            const float* W2 = cmW2 + (size_t)h * HIDd * Ff;
            float p = 0.f;
            #pragma unroll 4
            for (int tt = qt * 32; tt < qt * 32 + 32; tt++)
                p = fmaf(sHc[tt], W2[tt * Ff + f], p);
            sred[qt * 64 + f] = p;
        }
        __syncthreads();
        if (t < Ff) {
            float s = ssum0[0] * cmb2[h * Ff + t];
            #pragma unroll
            for (int q = 0; q < 8; q++) s += sred[q * 64 + t];
            sout[t] += s;
        }
        __syncthreads();
    }

    if (t < Ff) out[g * Ff + t] = sout[t] * (1.f / Hh);
}

// ---------------------------------------------------------------------------

extern "C" void kernel_launch(void* const* d_in, const int* in_sizes, int n_in,
                              void* d_out, int out_size) {
    const float* elem_weights = (const float*)d_in[0];
    const float* elem_fea_in  = (const float*)d_in[1];
    const float* W_init = (const float*)d_in[2];
    const float* b_init = (const float*)d_in[3];
    const float* mg_W1  = (const float*)d_in[4];
    const float* mg_b1  = (const float*)d_in[5];
    const float* mg_W2  = (const float*)d_in[6];
    const float* mg_b2  = (const float*)d_in[7];
    const float* mm_W1  = (const float*)d_in[8];
    const float* mm_b1  = (const float*)d_in[9];
    const float* mm_W2  = (const float*)d_in[10];
    const float* mm_b2  = (const float*)d_in[11];
    const float* m_pow  = (const float*)d_in[12];
    const float* cg_W1  = (const float*)d_in[13];
    const float* cg_b1  = (const float*)d_in[14];
    const float* cg_W2  = (const float*)d_in[15];
    const float* cg_b2  = (const float*)d_in[16];
    const float* cm_W1  = (const float*)d_in[17];
    const float* cm_b1  = (const float*)d_in[18];
    const float* cm_W2  = (const float*)d_in[19];
    const float* cm_b2  = (const float*)d_in[20];
    const float* c_pow  = (const float*)d_in[21];
    // d_in[22] = batch, d_in[23] = self_idx, d_in[24] = nbr_idx: implicit
    float* out = (float*)d_out;

    const int SMEM = (1024 + 4 * 16 * S + 16 * 5 + 64 + 512)
                     * (int)sizeof(float);  // 73280 B
    cudaFuncSetAttribute((const void*)fused_kernel,
                         cudaFuncAttributeMaxDynamicSharedMemorySize, SMEM);

    fused_kernel<<<Gg, 512, SMEM>>>(
        elem_weights, elem_fea_in, W_init, b_init,
        mg_W1, mg_b1, mg_W2, mg_b2, mm_W1, mm_b1, mm_W2, mm_b2, m_pow,
        cg_W1, cg_b1, cg_W2, cg_b2, cm_W1, cm_b1, cm_W2, cm_b2, c_pow,
        out);
}